// round 11
// baseline (speedup 1.0000x reference)
#include <cuda_runtime.h>
#include <cuda_bf16.h>
#include <cuda_fp16.h>
#include <cstdint>
#include <math.h>

// ---------------- problem constants ----------------
#define BB 4
#define TT 1024
#define EE 768
#define HH 12
#define LL 4
#define VV 50257
#define HDIM 64
#define NROWS (BB*TT)          // 4096

typedef __nv_bfloat16 bf16;

// ---------------- scratch (device globals) ----------------
__device__ float g_x  [NROWS*EE];
__device__ float g_att[(size_t)BB*HH*TT*TT];
__device__ float g_nll[NROWS];
__device__ float g_vld[NROWS];

__device__ bf16 g_xn_h [NROWS*EE],    g_xn_l [NROWS*EE];
__device__ bf16 g_qkv_h[NROWS*3*EE],  g_qkv_l[NROWS*3*EE];
__device__ bf16 g_ap_h [(size_t)BB*HH*TT*TT], g_ap_l[(size_t)BB*HH*TT*TT];
__device__ bf16 g_vT_h [(size_t)BB*HH*HDIM*TT], g_vT_l[(size_t)BB*HH*HDIM*TT];
__device__ bf16 g_y_h  [NROWS*EE],    g_y_l  [NROWS*EE];
__device__ bf16 g_h_h  [NROWS*4*EE],  g_h_l  [NROWS*4*EE];

__device__ __half g_wte_f[(size_t)VV*EE];   // fp16 wte for lm-head
__device__ __half g_xn_f [NROWS*EE];        // fp16 final-LN activations

__device__ bf16 g_aw_h [LL*3*EE*EE],     g_aw_l [LL*3*EE*EE];
__device__ bf16 g_pw_h [LL*EE*EE],       g_pw_l [LL*EE*EE];
__device__ bf16 g_fw_h [LL*4*EE*EE],     g_fw_l [LL*4*EE*EE];
__device__ bf16 g_mw_h [LL*4*EE*EE],     g_mw_l [LL*4*EE*EE];

// ---------------- helpers ----------------
__device__ __forceinline__ uint32_t pk2(bf16 a, bf16 b){
    __nv_bfloat162 t = __halves2bfloat162(a, b);
    return *reinterpret_cast<uint32_t*>(&t);
}
__device__ __forceinline__ void split1(float v, bf16& h, bf16& l){
    h = __float2bfloat16_rn(v);
    l = __float2bfloat16_rn(v - __bfloat162float(h));
}

__global__ void split4_k(const float4* __restrict__ in, uint32_t* __restrict__ oh,
                         uint32_t* __restrict__ ol, int n4)
{
    int i = blockIdx.x*256 + threadIdx.x;
    if (i >= n4) return;
    float4 v = in[i];
    bf16 h0,h1,h2,h3,l0,l1,l2,l3;
    split1(v.x,h0,l0); split1(v.y,h1,l1); split1(v.z,h2,l2); split1(v.w,h3,l3);
    oh[2*i] = pk2(h0,h1); oh[2*i+1] = pk2(h2,h3);
    ol[2*i] = pk2(l0,l1); ol[2*i+1] = pk2(l2,l3);
}

__global__ void tohalf4_k(const float4* __restrict__ in, __half2* __restrict__ o, int n4)
{
    int i = blockIdx.x*256 + threadIdx.x;
    if (i >= n4) return;
    float4 v = in[i];
    o[2*i]   = __floats2half2_rn(v.x, v.y);
    o[2*i+1] = __floats2half2_rn(v.z, v.w);
}

// ---------------- GEMM (NT, pre-split bf16x3) — proven R6 kernel ----------------
#define BM 128
#define BN 128
#define BK 32
#define RS 40                   // bf16 per smem row (80B) -> conflict-free ldmatrix
#define OPW (128*RS)            // bf16 per operand per stage
#define STG (4*OPW)             // Ah Al Bh Bl
#define NSTAGE 3
#define SMEMB (NSTAGE*STG*2)    // 122880 bytes

__device__ __forceinline__ void cpa16(uint32_t dst, const void* src, int sz){
    asm volatile("cp.async.cg.shared.global [%0], [%1], 16, %2;\n"
                 :: "r"(dst), "l"(src), "r"(sz));
}
__device__ __forceinline__ void ldsm4(uint32_t& r0, uint32_t& r1, uint32_t& r2,
                                      uint32_t& r3, uint32_t a){
    asm volatile("ldmatrix.sync.aligned.m8n8.x4.shared.b16 {%0,%1,%2,%3}, [%4];\n"
                 : "=r"(r0),"=r"(r1),"=r"(r2),"=r"(r3) : "r"(a));
}
__device__ __forceinline__ void ldsm2(uint32_t& r0, uint32_t& r1, uint32_t a){
    asm volatile("ldmatrix.sync.aligned.m8n8.x2.shared.b16 {%0,%1}, [%2];\n"
                 : "=r"(r0),"=r"(r1) : "r"(a));
}
#define MMA_BF16(Cc, A0,A1,A2,A3, B0,B1)                                     \
    asm volatile("mma.sync.aligned.m16n8k16.row.col.f32.bf16.bf16.f32 "      \
        "{%0,%1,%2,%3}, {%4,%5,%6,%7}, {%8,%9}, {%0,%1,%2,%3};\n"            \
        : "+f"(Cc[0]), "+f"(Cc[1]), "+f"(Cc[2]), "+f"(Cc[3])                 \
        : "r"(A0), "r"(A1), "r"(A2), "r"(A3), "r"(B0), "r"(B1));
#define MMA_F16(Cc, A0,A1,A2,A3, B0,B1)                                      \
    asm volatile("mma.sync.aligned.m16n8k16.row.col.f32.f16.f16.f32 "        \
        "{%0,%1,%2,%3}, {%4,%5,%6,%7}, {%8,%9}, {%0,%1,%2,%3};\n"            \
        : "+f"(Cc[0]), "+f"(Cc[1]), "+f"(Cc[2]), "+f"(Cc[3])                 \
        : "r"(A0), "r"(A1), "r"(A2), "r"(A3), "r"(B0), "r"(B1));

// MODE: 0 = +bias -> hi/lo (QKV)   1 = +bias,GELU -> hi/lo (fc)
//       2 = +bias+residual -> f32  3 = *scale, causal mask -> f32 (skip upper)
//       4 = -> hi/lo, K trimmed
template<int MODE>
__global__ void __launch_bounds__(256)
gemm_nt(const bf16* __restrict__ Ah, const bf16* __restrict__ Al,
        long sAo, long sAi, int lda,
        const bf16* __restrict__ Bh, const bf16* __restrict__ Bl,
        long sBo, long sBi, int ldb,
        float* __restrict__ Cf, bf16* __restrict__ Ch, bf16* __restrict__ Cl,
        long sCo, long sCi, int ldc,
        const float* __restrict__ bias, const float* __restrict__ Res, int ldr,
        int M, int N, int K, int innerCnt, float scale)
{
    int bn = blockIdx.x, bm = blockIdx.y, bz = blockIdx.z;
    if (MODE == 3 && bn > bm) return;       // causal: whole block above diagonal
    int zo = bz / innerCnt, zi = bz - zo*innerCnt;
    long ao = zo*sAo + zi*sAi, bo = zo*sBo + zi*sBi, co = zo*sCo + zi*sCi;

    extern __shared__ bf16 sm[];
    uint32_t smb = (uint32_t)__cvta_generic_to_shared(sm);

    int Keff = (MODE == 4) ? min(K, (bm+1)*BM) : K;
    int KT = Keff / BK;

    int tid = threadIdx.x;
    const bf16* Abh = Ah + ao + (long)bm*BM*lda;
    const bf16* Abl = Al + ao + (long)bm*BM*lda;
    const bf16* Bbh = Bh + bo + (long)bn*BN*ldb;
    const bf16* Bbl = Bl + bo + (long)bn*BN*ldb;
    int nbase = bn*BN;

    int seg = tid & 3;
    int row0 = tid >> 2, row1 = (tid + 256) >> 2;

    auto load_stage = [&](int s, int kt){
        int k0 = kt*BK;
        uint32_t base = smb + (uint32_t)s*STG*2;
        #pragma unroll
        for (int c = 0; c < 2; c++){
            int row = c ? row1 : row0;
            uint32_t so = (uint32_t)(row*RS + seg*8)*2;
            long go = (long)row*lda + k0 + seg*8;
            cpa16(base + so,            Abh + go, 16);
            cpa16(base + OPW*2 + so,    Abl + go, 16);
            int bsz = (nbase + row < N) ? 16 : 0;
            long gb = (long)row*ldb + k0 + seg*8;
            cpa16(base + 2*OPW*2 + so,  Bbh + gb, bsz);
            cpa16(base + 3*OPW*2 + so,  Bbl + gb, bsz);
        }
    };

    load_stage(0, 0);
    asm volatile("cp.async.commit_group;\n");
    load_stage(1, 1);
    asm volatile("cp.async.commit_group;\n");

    float c[4][4][4];
    #pragma unroll
    for (int i=0;i<4;i++)
        #pragma unroll
        for (int j=0;j<4;j++){ c[i][j][0]=0.f;c[i][j][1]=0.f;c[i][j][2]=0.f;c[i][j][3]=0.f; }

    int lane = tid & 31, wid = tid >> 5;
    int wm = (wid >> 2) * 64;
    int wn = (wid & 3) * 32;
    int gq = lane >> 2, tg = lane & 3;
    int aR = lane & 15,        aC = (lane >> 4) * 8;
    int bR = lane & 7,         bC = ((lane >> 3) & 1) * 8;

    for (int kt = 0; kt < KT; kt++){
        __syncthreads();
        if (kt + 2 < KT) load_stage((kt+2)%NSTAGE, kt+2);
        asm volatile("cp.async.commit_group;\n");
        asm volatile("cp.async.wait_group 1;\n");
        __syncthreads();

        uint32_t base = smb + (uint32_t)(kt % NSTAGE)*STG*2;
        uint32_t baseAh = base,            baseAl = base + OPW*2;
        uint32_t baseBh = base + 2*OPW*2,  baseBl = base + 3*OPW*2;

        #pragma unroll
        for (int ks = 0; ks < 2; ks++){
            int kc0 = ks*16;
            uint32_t ah[4][4], bh[4][2];
            #pragma unroll
            for (int i=0;i<4;i++)
                ldsm4(ah[i][0],ah[i][1],ah[i][2],ah[i][3],
                      baseAh + (uint32_t)((wm + i*16 + aR)*RS + kc0 + aC)*2);
            #pragma unroll
            for (int j=0;j<4;j++)
                ldsm2(bh[j][0],bh[j][1],
                      baseBh + (uint32_t)((wn + j*8 + bR)*RS + kc0 + bC)*2);
            #pragma unroll
            for (int i=0;i<4;i++)
                #pragma unroll
                for (int j=0;j<4;j++)
                    MMA_BF16(c[i][j], ah[i][0],ah[i][1],ah[i][2],ah[i][3], bh[j][0],bh[j][1]);

            uint32_t bl[4][2];
            #pragma unroll
            for (int j=0;j<4;j++)
                ldsm2(bl[j][0],bl[j][1],
                      baseBl + (uint32_t)((wn + j*8 + bR)*RS + kc0 + bC)*2);
            #pragma unroll
            for (int i=0;i<4;i++)
                #pragma unroll
                for (int j=0;j<4;j++)
                    MMA_BF16(c[i][j], ah[i][0],ah[i][1],ah[i][2],ah[i][3], bl[j][0],bl[j][1]);

            uint32_t al[4][4];
            #pragma unroll
            for (int i=0;i<4;i++)
                ldsm4(al[i][0],al[i][1],al[i][2],al[i][3],
                      baseAl + (uint32_t)((wm + i*16 + aR)*RS + kc0 + aC)*2);
            #pragma unroll
            for (int i=0;i<4;i++)
                #pragma unroll
                for (int j=0;j<4;j++)
                    MMA_BF16(c[i][j], al[i][0],al[i][1],al[i][2],al[i][3], bh[j][0],bh[j][1]);
        }
    }

    #pragma unroll
    for (int i=0;i<4;i++){
        int r0 = bm*BM + wm + i*16 + gq;
        #pragma unroll
        for (int j=0;j<4;j++){
            int c0 = nbase + wn + j*8 + tg*2;
            #pragma unroll
            for (int h2=0; h2<2; h2++){
                int rr = r0 + h2*8;
                #pragma unroll
                for (int cc=0; cc<2; cc++){
                    int col = c0 + cc;
                    if (col >= N) continue;
                    float v = c[i][j][h2*2 + cc];
                    long oidx = co + (long)rr*ldc + col;
                    if (MODE == 0){
                        v += bias[col];
                        bf16 h, l; split1(v, h, l);
                        Ch[oidx] = h; Cl[oidx] = l;
                    } else if (MODE == 1){
                        v += bias[col];
                        v = 0.5f*v*(1.f + erff(v*0.70710678118654752f));
                        bf16 h, l; split1(v, h, l);
                        Ch[oidx] = h; Cl[oidx] = l;
                    } else if (MODE == 2){
                        v += bias[col] + Res[(long)rr*ldr + col];
                        Cf[oidx] = v;
                    } else if (MODE == 3){
                        v *= scale; if (col > rr) v = -1e30f;
                        Cf[oidx] = v;
                    } else if (MODE == 4){
                        bf16 h, l; split1(v, h, l);
                        Ch[oidx] = h; Cl[oidx] = l;
                    }
                }
            }
        }
    }
}

// ---------------- lm-head GEMM: single-pass fp16 ----------------
// C[M,N] = A[M,K] @ B[N,K]^T,  A,B fp16, C fp32.  K=768, lda=ldb=768, ldc=VV.
#define OPW2 (128*RS)               // halves per operand per stage
#define STG2 (2*OPW2)               // Ah Bh
#define SMEM2 (NSTAGE*STG2*2)       // 61440 bytes

__global__ void __launch_bounds__(256)
gemm_lm(const __half* __restrict__ A, const __half* __restrict__ Bm,
        float* __restrict__ C, int N)
{
    int bm = blockIdx.x, bn = blockIdx.y;   // bm fastest -> wte tile reuse in L2
    const int K = EE, KT = K / BK;

    extern __shared__ __half sm2[];
    uint32_t smb = (uint32_t)__cvta_generic_to_shared(sm2);

    int tid = threadIdx.x;
    const __half* Ab = A  + (long)bm*BM*K;
    const __half* Bb = Bm + (long)bn*BN*K;
    int nbase = bn*BN;

    int seg = tid & 3;
    int row0 = tid >> 2, row1 = (tid + 256) >> 2;

    auto load_stage = [&](int s, int kt){
        int k0 = kt*BK;
        uint32_t base = smb + (uint32_t)s*STG2*2;
        #pragma unroll
        for (int c = 0; c < 2; c++){
            int row = c ? row1 : row0;
            uint32_t so = (uint32_t)(row*RS + seg*8)*2;
            cpa16(base + so, Ab + (long)row*K + k0 + seg*8, 16);
            int bsz = (nbase + row < N) ? 16 : 0;
            cpa16(base + OPW2*2 + so, Bb + (long)row*K + k0 + seg*8, bsz);
        }
    };

    load_stage(0, 0);
    asm volatile("cp.async.commit_group;\n");
    load_stage(1, 1);
    asm volatile("cp.async.commit_group;\n");

    float c[4][4][4];
    #pragma unroll
    for (int i=0;i<4;i++)
        #pragma unroll
        for (int j=0;j<4;j++){ c[i][j][0]=0.f;c[i][j][1]=0.f;c[i][j][2]=0.f;c[i][j][3]=0.f; }

    int lane = tid & 31, wid = tid >> 5;
    int wm = (wid >> 2) * 64;
    int wn = (wid & 3) * 32;
    int gq = lane >> 2, tg = lane & 3;
    int aR = lane & 15,        aC = (lane >> 4) * 8;
    int bR = lane & 7,         bC = ((lane >> 3) & 1) * 8;

    for (int kt = 0; kt < KT; kt++){
        __syncthreads();
        if (kt + 2 < KT) load_stage((kt+2)%NSTAGE, kt+2);
        asm volatile("cp.async.commit_group;\n");
        asm volatile("cp.async.wait_group 1;\n");
        __syncthreads();

        uint32_t base = smb + (uint32_t)(kt % NSTAGE)*STG2*2;
        uint32_t baseA = base, baseB = base + OPW2*2;

        #pragma unroll
        for (int ks = 0; ks < 2; ks++){
            int kc0 = ks*16;
            uint32_t ah[4][4], bh[4][2];
            #pragma unroll
            for (int i=0;i<4;i++)
                ldsm4(ah[i][0],ah[i][1],ah[i][2],ah[i][3],
                      baseA + (uint32_t)((wm + i*16 + aR)*RS + kc0 + aC)*2);
            #pragma unroll
            for (int j=0;j<4;j++)
                ldsm2(bh[j][0],bh[j][1],
                      baseB + (uint32_t)((wn + j*8 + bR)*RS + kc0 + bC)*2);
            #pragma unroll
            for (int i=0;i<4;i++)
                #pragma unroll
                for (int j=0;j<4;j++)
                    MMA_F16(c[i][j], ah[i][0],ah[i][1],ah[i][2],ah[i][3], bh[j][0],bh[j][1]);
        }
    }

    #pragma unroll
    for (int i=0;i<4;i++){
        int r0 = bm*BM + wm + i*16 + gq;
        #pragma unroll
        for (int j=0;j<4;j++){
            int c0 = nbase + wn + j*8 + tg*2;
            #pragma unroll
            for (int h2=0; h2<2; h2++){
                long rb = (long)(r0 + h2*8)*VV;
                #pragma unroll
                for (int cc=0; cc<2; cc++){
                    int col = c0 + cc;
                    if (col < N) C[rb + col] = c[i][j][h2*2 + cc];
                }
            }
        }
    }
}

// ---------------- embedding ----------------
__global__ void embed_k(const int* __restrict__ idx, const float* __restrict__ wte,
                        const float* __restrict__ wpe, float* __restrict__ x)
{
    int i = blockIdx.x*256 + threadIdx.x;
    if (i >= NROWS*EE) return;
    int row = i / EE, col = i - row*EE;
    int t = row & (TT-1);
    x[i] = wte[(long)idx[row]*EE + col] + wpe[(long)t*EE + col];
}

// ---------------- layernorm -> hi/lo bf16 ----------------
__global__ void layernorm_k(const float* __restrict__ x, const float* __restrict__ w,
                            const float* __restrict__ b,
                            bf16* __restrict__ oh, bf16* __restrict__ ol)
{
    int row = blockIdx.x;
    const float* xr = x + (long)row*EE;
    long obase = (long)row*EE;
    int tid = threadIdx.x;
    float v0 = xr[tid], v1 = xr[tid+256], v2 = xr[tid+512];
    float s = v0+v1+v2, q = v0*v0+v1*v1+v2*v2;
    __shared__ float sh1[256], sh2[256];
    sh1[tid]=s; sh2[tid]=q; __syncthreads();
    #pragma unroll
    for (int off=128; off>0; off>>=1){
        if (tid < off){ sh1[tid]+=sh1[tid+off]; sh2[tid]+=sh2[tid+off]; }
        __syncthreads();
    }
    float mean = sh1[0]*(1.f/EE);
    float var  = sh2[0]*(1.f/EE) - mean*mean;
    float rstd = rsqrtf(var + 1e-5f);
    #pragma unroll
    for (int p = 0; p < 3; p++){
        int cidx = tid + p*256;
        float vv = (p==0? v0 : p==1? v1 : v2);
        float val = (vv-mean)*rstd*w[cidx] + b[cidx];
        bf16 h, l; split1(val, h, l);
        oh[obase+cidx] = h; ol[obase+cidx] = l;
    }
}

// ---------------- final layernorm -> fp16 ----------------
__global__ void layernorm_f16(const float* __restrict__ x, const float* __restrict__ w,
                              const float* __restrict__ b, __half* __restrict__ o)
{
    int row = blockIdx.x;
    const float* xr = x + (long)row*EE;
    long obase = (long)row*EE;
    int tid = threadIdx.x;
    float v0 = xr[tid], v1 = xr[tid+256], v2 = xr[tid+512];
    float s = v0+v1+v2, q = v0*v0+v1*v1+v2*v2;
    __shared__ float sh1[256], sh2[256];
    sh1[tid]=s; sh2[tid]=q; __syncthreads();
    #pragma unroll
    for (int off=128; off>0; off>>=1){
        if (tid < off){ sh1[tid]+=sh1[tid+off]; sh2[tid]+=sh2[tid+off]; }
        __syncthreads();
    }
    float mean = sh1[0]*(1.f/EE);
    float var  = sh2[0]*(1.f/EE) - mean*mean;
    float rstd = rsqrtf(var + 1e-5f);
    #pragma unroll
    for (int p = 0; p < 3; p++){
        int cidx = tid + p*256;
        float vv = (p==0? v0 : p==1? v1 : v2);
        o[obase+cidx] = __float2half_rn((vv-mean)*rstd*w[cidx] + b[cidx]);
    }
}

// ---------------- V transpose (hi & lo) ----------------
__global__ void transpose_v(const bf16* __restrict__ qh, const bf16* __restrict__ ql,
                            bf16* __restrict__ vh, bf16* __restrict__ vl)
{
    int z = blockIdx.y; int b = z/HH, h = z - b*HH;
    int k0 = blockIdx.x * 64;
    __shared__ bf16 th[64][72], tl[64][72];
    const long sbase = ((long)(b*TT + k0))*(3*EE) + 2*EE + h*HDIM;
    int tid = threadIdx.x;
    #pragma unroll
    for (int i=0;i<16;i++){
        int id = tid + i*256;
        int kr = id >> 6, d = id & 63;
        th[kr][d] = qh[sbase + (long)kr*(3*EE) + d];
        tl[kr][d] = ql[sbase + (long)kr*(3*EE) + d];
    }
    __syncthreads();
    long dbase = (long)z*HDIM*TT + k0;
    #pragma unroll
    for (int i=0;i<16;i++){
        int id = tid + i*256;
        int d = id >> 6, kc = id & 63;
        vh[dbase + (long)d*TT + kc] = th[kc][d];
        vl[dbase + (long)d*TT + kc] = tl[kc][d];
    }
}

// ---------------- causal row softmax -> hi/lo probs ----------------
__global__ void softmax_causal(const float* __restrict__ att,
                               bf16* __restrict__ ph, bf16* __restrict__ pl)
{
    int rid = blockIdx.x;
    int z = rid >> 10, q = rid & (TT-1);
    long base = (long)z*TT*TT + (long)q*TT;
    const float* p = att + base;
    int kend = ((q >> 7) + 1) << 7;
    int tid = threadIdx.x;
    float v[4];
    float m = -1e30f;
    #pragma unroll
    for (int i=0;i<4;i++){
        int k = tid + i*256;
        v[i] = (k < kend) ? p[k] : -1e30f;
        m = fmaxf(m, v[i]);
    }
    __shared__ float sh[256];
    sh[tid] = m; __syncthreads();
    #pragma unroll
    for (int off=128; off>0; off>>=1){
        if (tid < off) sh[tid] = fmaxf(sh[tid], sh[tid+off]);
        __syncthreads();
    }
    m = sh[0]; __syncthreads();
    float s = 0.f;
    #pragma unroll
    for (int i=0;i<4;i++){ v[i] = __expf(v[i] - m); s += v[i]; }
    sh[tid] = s; __syncthreads();
    #pragma unroll
    for (int off=128; off>0; off>>=1){
        if (tid < off) sh[tid] += sh[tid+off];
        __syncthreads();
    }
    float inv = 1.f / sh[0];
    #pragma unroll
    for (int i=0;i<4;i++){
        int k = tid + i*256;
        if (k < kend){
            float val = v[i]*inv;
            bf16 h, l; split1(val, h, l);
            ph[base+k] = h; pl[base+k] = l;
        }
    }
}

// ---------------- loss ----------------
__global__ void loss_rows(const float* __restrict__ lg, const int* __restrict__ tgt,
                          float* __restrict__ nll, float* __restrict__ vld)
{
    long row = blockIdx.x;
    const float* p = lg + row*(long)VV;
    int tid = threadIdx.x;
    float m = -3.0e38f, s = 0.f;
    for (int k = tid; k < VV; k += 256){
        float x = p[k];
        if (x > m){ s = s*__expf(m - x) + 1.f; m = x; }
        else s += __expf(x - m);
    }
    __shared__ float sm[256], ss[256];
    sm[tid]=m; ss[tid]=s; __syncthreads();
    #pragma unroll
    for (int off=128; off>0; off>>=1){
        if (tid < off){
            float m2 = sm[tid+off], s2 = ss[tid+off];
            float mm = fmaxf(sm[tid], m2);
            ss[tid] = ss[tid]*__expf(sm[tid]-mm) + s2*__expf(m2-mm);
            sm[tid] = mm;
        }
        __syncthreads();
    }
    if (tid == 0){
        float lse = sm[0] + logf(ss[0]);
        int t = tgt[row];
        if (t != -1){ nll[row] = lse - p[t]; vld[row] = 1.f; }
        else        { nll[row] = 0.f;       vld[row] = 0.f; }
    }
}

__global__ void loss_final(const float* __restrict__ nll, const float* __restrict__ vld,
                           float* __restrict__ out)
{
    int tid = threadIdx.x;
    float a = 0.f, b = 0.f;
    for (int i = tid; i < NROWS; i += 256){ a += nll[i]; b += vld[i]; }
    __shared__ float s1[256], s2[256];
    s1[tid]=a; s2[tid]=b; __syncthreads();
    #pragma unroll
    for (int off=128; off>0; off>>=1){
        if (tid < off){ s1[tid]+=s1[tid+off]; s2[tid]+=s2[tid+off]; }
        __syncthreads();
    }
    if (tid == 0) out[0] = s1[0] / fmaxf(s2[0], 1.f);
}

// ---------------- host ----------------
static void split_arr(const float* src, bf16* h, bf16* l, long n){
    int n4 = (int)(n/4);
    split4_k<<<(n4 + 255)/256, 256>>>((const float4*)src, (uint32_t*)h, (uint32_t*)l, n4);
}

extern "C" void kernel_launch(void* const* d_in, const int* in_sizes, int n_in,
                              void* d_out, int out_size)
{
    const int*   idx     = (const int*)  d_in[0];
    const int*   tgt     = (const int*)  d_in[1];
    const float* wte     = (const float*)d_in[2];
    const float* wpe     = (const float*)d_in[3];
    const float* ln1_w   = (const float*)d_in[4];
    const float* ln1_b   = (const float*)d_in[5];
    const float* attn_w  = (const float*)d_in[6];
    const float* attn_b  = (const float*)d_in[7];
    const float* aproj_w = (const float*)d_in[8];
    const float* aproj_b = (const float*)d_in[9];
    const float* ln2_w   = (const float*)d_in[10];
    const float* ln2_b   = (const float*)d_in[11];
    const float* fc_w    = (const float*)d_in[12];
    const float* fc_b    = (const float*)d_in[13];
    const float* proj_w  = (const float*)d_in[14];
    const float* proj_b  = (const float*)d_in[15];
    const float* lnf_w   = (const float*)d_in[16];
    const float* lnf_b   = (const float*)d_in[17];
    float* out = (float*)d_out;

    float *x, *att, *nll, *vld;
    bf16 *xn_h,*xn_l,*qkv_h,*qkv_l,*ap_h,*ap_l,*vT_h,*vT_l,*y_h,*y_l,*h_h,*h_l;
    bf16 *aw_h,*aw_l,*pw_h,*pw_l,*fw_h,*fw_l,*mw_h,*mw_l;
    __half *wte_f, *xn_f;
    cudaGetSymbolAddress((void**)&x,    g_x);
    cudaGetSymbolAddress((void**)&att,  g_att);
    cudaGetSymbolAddress((void**)&nll,  g_nll);
    cudaGetSymbolAddress((void**)&vld,  g_vld);
    cudaGetSymbolAddress((void**)&xn_h, g_xn_h);  cudaGetSymbolAddress((void**)&xn_l, g_xn_l);
    cudaGetSymbolAddress((void**)&qkv_h,g_qkv_h); cudaGetSymbolAddress((void**)&qkv_l,g_qkv_l);
    cudaGetSymbolAddress((void**)&ap_h, g_ap_h);  cudaGetSymbolAddress((void**)&ap_l, g_ap_l);
    cudaGetSymbolAddress((void**)&vT_h, g_vT_h);  cudaGetSymbolAddress((void**)&vT_l, g_vT_l);
    cudaGetSymbolAddress((void**)&y_h,  g_y_h);   cudaGetSymbolAddress((void**)&y_l,  g_y_l);
    cudaGetSymbolAddress((void**)&h_h,  g_h_h);   cudaGetSymbolAddress((void**)&h_l,  g_h_l);
    cudaGetSymbolAddress((void**)&aw_h, g_aw_h);  cudaGetSymbolAddress((void**)&aw_l, g_aw_l);
    cudaGetSymbolAddress((void**)&pw_h, g_pw_h);  cudaGetSymbolAddress((void**)&pw_l, g_pw_l);
    cudaGetSymbolAddress((void**)&fw_h, g_fw_h);  cudaGetSymbolAddress((void**)&fw_l, g_fw_l);
    cudaGetSymbolAddress((void**)&mw_h, g_mw_h);  cudaGetSymbolAddress((void**)&mw_l, g_mw_l);
    cudaGetSymbolAddress((void**)&wte_f, g_wte_f);
    cudaGetSymbolAddress((void**)&xn_f,  g_xn_f);

    cudaFuncSetAttribute(gemm_nt<0>, cudaFuncAttributeMaxDynamicSharedMemorySize, SMEMB);
    cudaFuncSetAttribute(gemm_nt<1>, cudaFuncAttributeMaxDynamicSharedMemorySize, SMEMB);
    cudaFuncSetAttribute(gemm_nt<2>, cudaFuncAttributeMaxDynamicSharedMemorySize, SMEMB);
    cudaFuncSetAttribute(gemm_nt<3>, cudaFuncAttributeMaxDynamicSharedMemorySize, SMEMB);
    cudaFuncSetAttribute(gemm_nt<4>, cudaFuncAttributeMaxDynamicSharedMemorySize, SMEMB);
    cudaFuncSetAttribute(gemm_lm,    cudaFuncAttributeMaxDynamicSharedMemorySize, SMEM2);

    // one-shot weight preprocessing
    split_arr(attn_w,  aw_h, aw_l, (long)LL*3*EE*EE);
    split_arr(aproj_w, pw_h, pw_l, (long)LL*EE*EE);
    split_arr(fc_w,    fw_h, fw_l, (long)LL*4*EE*EE);
    split_arr(proj_w,  mw_h, mw_l, (long)LL*4*EE*EE);
    {
        long n4 = (long)VV*EE/4;
        tohalf4_k<<<(int)((n4 + 255)/256), 256>>>((const float4*)wte, (__half2*)wte_f, (int)n4);
    }

    embed_k<<<(NROWS*EE + 255)/256, 256>>>(idx, wte, wpe, x);

    for (int l = 0; l < LL; l++){
        layernorm_k<<<NROWS, 256>>>(x, ln1_w + l*EE, ln1_b + l*EE, xn_h, xn_l);

        gemm_nt<0><<<dim3(3*EE/BN, NROWS/BM, 1), 256, SMEMB>>>(
            xn_h, xn_l, 0, 0, EE,
            aw_h + (long)l*3*EE*EE, aw_l + (long)l*3*EE*EE, 0, 0, EE,
            nullptr, qkv_h, qkv_l, 0, 0, 3*EE,
            attn_b + (long)l*3*EE, nullptr, 0,
            NROWS, 3*EE, EE, 1, 1.f);

        transpose_v<<<dim3(TT/64, BB*HH), 256>>>(qkv_h, qkv_l, vT_h, vT_l);

        gemm_nt<3><<<dim3(TT/BN, TT/BM, BB*HH), 256, SMEMB>>>(
            qkv_h,      qkv_l,      (long)TT*3*EE, HDIM, 3*EE,
            qkv_h + EE, qkv_l + EE, (long)TT*3*EE, HDIM, 3*EE,
            att, nullptr, nullptr, (long)HH*TT*TT, (long)TT*TT, TT,
            nullptr, nullptr, 0,
            TT, TT, HDIM, HH, 0.125f);

        softmax_causal<<<BB*HH*TT, 256>>>(att, ap_h, ap_l);

        gemm_nt<4><<<dim3(1, TT/BM, BB*HH), 256, SMEMB>>>(
            ap_h, ap_l, (long)HH*TT*TT,   (long)TT*TT,   TT,
            vT_h, vT_l, (long)HH*HDIM*TT, (long)HDIM*TT, TT,
            nullptr, y_h, y_l, (long)TT*EE, HDIM, EE,
            nullptr, nullptr, 0,
            TT, HDIM, TT, HH, 1.f);

        gemm_nt<2><<<dim3(EE/BN, NROWS/BM, 1), 256, SMEMB>>>(
            y_h, y_l, 0, 0, EE,
            pw_h + (long)l*EE*EE, pw_l + (long)l*EE*EE, 0, 0, EE,
            x, nullptr, nullptr, 0, 0, EE,
            aproj_b + (long)l*EE, x, EE,
            NROWS, EE, EE, 1, 1.f);

        layernorm_k<<<NROWS, 256>>>(x, ln2_w + l*EE, ln2_b + l*EE, xn_h, xn_l);

        gemm_nt<1><<<dim3(4*EE/BN, NROWS/BM, 1), 256, SMEMB>>>(
            xn_h, xn_l, 0, 0, EE,
            fw_h + (long)l*4*EE*EE, fw_l + (long)l*4*EE*EE, 0, 0, EE,
            nullptr, h_h, h_l, 0, 0, 4*EE,
            fc_b + (long)l*4*EE, nullptr, 0,
            NROWS, 4*EE, EE, 1, 1.f);

        gemm_nt<2><<<dim3(EE/BN, NROWS/BM, 1), 256, SMEMB>>>(
            h_h, h_l, 0, 0, 4*EE,
            mw_h + (long)l*4*EE*EE, mw_l + (long)l*4*EE*EE, 0, 0, 4*EE,
            x, nullptr, nullptr, 0, 0, EE,
            proj_b + (long)l*EE, x, EE,
            NROWS, EE, 4*EE, 1, 1.f);
    }

    layernorm_f16<<<NROWS, 256>>>(x, lnf_w, lnf_b, xn_f);

    // logits = xn @ wte^T (fp16 single-pass) -> d_out
    gemm_lm<<<dim3(NROWS/BM, (VV + BN - 1)/BN, 1), 256, SMEM2>>>(
        xn_f, wte_f, out, VV);

    long BTV = (long)NROWS * VV;
    if ((long)out_size > BTV){
        loss_rows<<<NROWS, 256>>>(out, tgt, nll, vld);
        loss_final<<<1, 256>>>(nll, vld, out + BTV);
    }
}

// round 13
// speedup vs baseline: 2.0054x; 2.0054x over previous
#include <cuda_runtime.h>
#include <cuda_fp16.h>
#include <cstdint>
#include <math.h>

// ---------------- problem constants ----------------
#define BB 4
#define TT 1024
#define EE 768
#define HH 12
#define LL 4
#define VV 50257
#define HDIM 64
#define NROWS (BB*TT)          // 4096

// ---------------- scratch (device globals) ----------------
__device__ float g_x  [NROWS*EE];
__device__ float g_att[(size_t)BB*HH*TT*TT];
__device__ float g_nll[NROWS];
__device__ float g_vld[NROWS];

__device__ __half g_xn_f [NROWS*EE];                 // LN out (single fp16)
__device__ __half g_qkv_h[NROWS*3*EE], g_qkv_l[NROWS*3*EE];  // QKV hi/lo
__device__ __half g_p_f  [(size_t)BB*HH*TT*TT];      // softmax probs (single)
__device__ __half g_vT_h [(size_t)BB*HH*HDIM*TT], g_vT_l[(size_t)BB*HH*HDIM*TT];
__device__ __half g_y_f  [NROWS*EE];                 // AV out (single)
__device__ __half g_h_f  [NROWS*4*EE];               // fc out (single)

__device__ __half g_wte_f[(size_t)VV*EE];            // lm-head B (single)
__device__ __half g_aw_h [LL*3*EE*EE], g_aw_l [LL*3*EE*EE];
__device__ __half g_pw_h [LL*EE*EE],   g_pw_l [LL*EE*EE];
__device__ __half g_fw_h [LL*4*EE*EE], g_fw_l [LL*4*EE*EE];
__device__ __half g_mw_h [LL*4*EE*EE], g_mw_l [LL*4*EE*EE];

// ---------------- helpers ----------------
__device__ __forceinline__ void splitf(float v, __half& h, __half& l){
    h = __float2half_rn(v);
    l = __float2half_rn(v - __half2float(h));
}
__device__ __forceinline__ uint32_t pkh2(__half a, __half b){
    __half2 t = __halves2half2(a, b);
    return *reinterpret_cast<uint32_t*>(&t);
}

// fp32[n] -> fp16 hi/lo (n % 4 == 0)
__global__ void splitf4_k(const float4* __restrict__ in, uint32_t* __restrict__ oh,
                          uint32_t* __restrict__ ol, int n4)
{
    int i = blockIdx.x*256 + threadIdx.x;
    if (i >= n4) return;
    float4 v = in[i];
    __half h0,h1,h2,h3,l0,l1,l2,l3;
    splitf(v.x,h0,l0); splitf(v.y,h1,l1); splitf(v.z,h2,l2); splitf(v.w,h3,l3);
    oh[2*i] = pkh2(h0,h1); oh[2*i+1] = pkh2(h2,h3);
    ol[2*i] = pkh2(l0,l1); ol[2*i+1] = pkh2(l2,l3);
}

__global__ void tohalf4_k(const float4* __restrict__ in, __half2* __restrict__ o, int n4)
{
    int i = blockIdx.x*256 + threadIdx.x;
    if (i >= n4) return;
    float4 v = in[i];
    o[2*i]   = __floats2half2_rn(v.x, v.y);
    o[2*i+1] = __floats2half2_rn(v.z, v.w);
}

// ---------------- common GEMM machinery (proven R6 skeleton) ----------------
#define BM 128
#define BN 128
#define BK 32
#define RS 40                   // halves per smem row (80B) -> conflict-free ldmatrix
#define OPH (128*RS)            // halves per operand per stage
#define NSTAGE 3

__device__ __forceinline__ void cpa16(uint32_t dst, const void* src, int sz){
    asm volatile("cp.async.cg.shared.global [%0], [%1], 16, %2;\n"
                 :: "r"(dst), "l"(src), "r"(sz));
}
__device__ __forceinline__ void ldsm4(uint32_t& r0, uint32_t& r1, uint32_t& r2,
                                      uint32_t& r3, uint32_t a){
    asm volatile("ldmatrix.sync.aligned.m8n8.x4.shared.b16 {%0,%1,%2,%3}, [%4];\n"
                 : "=r"(r0),"=r"(r1),"=r"(r2),"=r"(r3) : "r"(a));
}
__device__ __forceinline__ void ldsm2(uint32_t& r0, uint32_t& r1, uint32_t a){
    asm volatile("ldmatrix.sync.aligned.m8n8.x2.shared.b16 {%0,%1}, [%2];\n"
                 : "=r"(r0),"=r"(r1) : "r"(a));
}
#define MMA_F16(Cc, A0,A1,A2,A3, B0,B1)                                      \
    asm volatile("mma.sync.aligned.m16n8k16.row.col.f32.f16.f16.f32 "        \
        "{%0,%1,%2,%3}, {%4,%5,%6,%7}, {%8,%9}, {%0,%1,%2,%3};\n"            \
        : "+f"(Cc[0]), "+f"(Cc[1]), "+f"(Cc[2]), "+f"(Cc[3])                 \
        : "r"(A0), "r"(A1), "r"(A2), "r"(A3), "r"(B0), "r"(B1));

// ---------------- layer GEMM: A single fp16, B split (Bh,Bl), 2 passes -------
// NT: A[M,K] K-major, B[N,K] K-major, C = A*(Bh+Bl)^T
#define STG3 (3*OPH)
#define SMEM3 (NSTAGE*STG3*2)   // 92160 bytes

// MODE: 0 = +bias -> hi/lo fp16 (QKV)   1 = +bias, GELU -> fp16 (fc)
//       2 = +bias+residual -> f32       3 = *scale, causal mask -> f32 (skip upper)
//       4 = -> fp16 single, K trimmed (AV)
template<int MODE>
__global__ void __launch_bounds__(256)
gemm_f2(const __half* __restrict__ A, long sAo, long sAi, int lda,
        const __half* __restrict__ Bh, const __half* __restrict__ Bl,
        long sBo, long sBi, int ldb,
        float* __restrict__ Cf, __half* __restrict__ Ch, __half* __restrict__ Cl,
        long sCo, long sCi, int ldc,
        const float* __restrict__ bias, const float* __restrict__ Res, int ldr,
        int M, int N, int K, int innerCnt, float scale)
{
    int bn = blockIdx.x, bm = blockIdx.y, bz = blockIdx.z;
    if (MODE == 3 && bn > bm) return;       // causal: block above diagonal
    int zo = bz / innerCnt, zi = bz - zo*innerCnt;
    long ao = zo*sAo + zi*sAi, bo = zo*sBo + zi*sBi, co = zo*sCo + zi*sCi;

    extern __shared__ __half sm[];
    uint32_t smb = (uint32_t)__cvta_generic_to_shared(sm);

    int Keff = (MODE == 4) ? min(K, (bm+1)*BM) : K;
    int KT = Keff / BK;

    int tid = threadIdx.x;
    const __half* Ab  = A  + ao + (long)bm*BM*lda;
    const __half* Bbh = Bh + bo + (long)bn*BN*ldb;
    const __half* Bbl = Bl + bo + (long)bn*BN*ldb;
    int nbase = bn*BN;

    int seg = tid & 3;
    int row0 = tid >> 2, row1 = (tid + 256) >> 2;

    auto load_stage = [&](int s, int kt){
        int k0 = kt*BK;
        uint32_t base = smb + (uint32_t)s*STG3*2;
        #pragma unroll
        for (int c = 0; c < 2; c++){
            int row = c ? row1 : row0;
            uint32_t so = (uint32_t)(row*RS + seg*8)*2;
            cpa16(base + so, Ab + (long)row*lda + k0 + seg*8, 16);
            int bsz = (nbase + row < N) ? 16 : 0;
            long gb = (long)row*ldb + k0 + seg*8;
            cpa16(base + OPH*2 + so,   Bbh + gb, bsz);
            cpa16(base + 2*OPH*2 + so, Bbl + gb, bsz);
        }
    };

    load_stage(0, 0);
    asm volatile("cp.async.commit_group;\n");
    load_stage(1, 1);
    asm volatile("cp.async.commit_group;\n");

    float c[4][4][4];
    #pragma unroll
    for (int i=0;i<4;i++)
        #pragma unroll
        for (int j=0;j<4;j++){ c[i][j][0]=0.f;c[i][j][1]=0.f;c[i][j][2]=0.f;c[i][j][3]=0.f; }

    int lane = tid & 31, wid = tid >> 5;
    int wm = (wid >> 2) * 64;
    int wn = (wid & 3) * 32;
    int gq = lane >> 2, tg = lane & 3;
    int aR = lane & 15,        aC = (lane >> 4) * 8;
    int bR = lane & 7,         bC = ((lane >> 3) & 1) * 8;

    for (int kt = 0; kt < KT; kt++){
        __syncthreads();
        if (kt + 2 < KT) load_stage((kt+2)%NSTAGE, kt+2);
        asm volatile("cp.async.commit_group;\n");
        asm volatile("cp.async.wait_group 1;\n");
        __syncthreads();

        uint32_t base   = smb + (uint32_t)(kt % NSTAGE)*STG3*2;
        uint32_t baseA  = base;
        uint32_t baseBh = base + OPH*2;
        uint32_t baseBl = base + 2*OPH*2;

        #pragma unroll
        for (int ks = 0; ks < 2; ks++){
            int kc0 = ks*16;
            uint32_t af[4][4], bh[4][2];
            #pragma unroll
            for (int i=0;i<4;i++)
                ldsm4(af[i][0],af[i][1],af[i][2],af[i][3],
                      baseA + (uint32_t)((wm + i*16 + aR)*RS + kc0 + aC)*2);
            #pragma unroll
            for (int j=0;j<4;j++)
                ldsm2(bh[j][0],bh[j][1],
                      baseBh + (uint32_t)((wn + j*8 + bR)*RS + kc0 + bC)*2);
            #pragma unroll
            for (int i=0;i<4;i++)
                #pragma unroll
                for (int j=0;j<4;j++)
                    MMA_F16(c[i][j], af[i][0],af[i][1],af[i][2],af[i][3], bh[j][0],bh[j][1]);

            uint32_t bl[4][2];
            #pragma unroll
            for (int j=0;j<4;j++)
                ldsm2(bl[j][0],bl[j][1],
                      baseBl + (uint32_t)((wn + j*8 + bR)*RS + kc0 + bC)*2);
            #pragma unroll
            for (int i=0;i<4;i++)
                #pragma unroll
                for (int j=0;j<4;j++)
                    MMA_F16(c[i][j], af[i][0],af[i][1],af[i][2],af[i][3], bl[j][0],bl[j][1]);
        }
    }

    #pragma unroll
    for (int i=0;i<4;i++){
        int r0 = bm*BM + wm + i*16 + gq;
        #pragma unroll
        for (int j=0;j<4;j++){
            int c0 = nbase + wn + j*8 + tg*2;
            #pragma unroll
            for (int h2=0; h2<2; h2++){
                int rr = r0 + h2*8;
                #pragma unroll
                for (int cc=0; cc<2; cc++){
                    int col = c0 + cc;
                    if (col >= N) continue;
                    float v = c[i][j][h2*2 + cc];
                    long oidx = co + (long)rr*ldc + col;
                    if (MODE == 0){
                        v += bias[col];
                        __half h, l; splitf(v, h, l);
                        Ch[oidx] = h; Cl[oidx] = l;
                    } else if (MODE == 1){
                        v += bias[col];
                        v = 0.5f*v*(1.f + erff(v*0.70710678118654752f));
                        Ch[oidx] = __float2half_rn(v);
                    } else if (MODE == 2){
                        v += bias[col] + Res[(long)rr*ldr + col];
                        Cf[oidx] = v;
                    } else if (MODE == 3){
                        v *= scale; if (col > rr) v = -1e30f;
                        Cf[oidx] = v;
                    } else if (MODE == 4){
                        Ch[oidx] = __float2half_rn(v);
                    }
                }
            }
        }
    }
}

// ---------------- lm-head GEMM: single-pass fp16 (A single, B single) --------
#define STG1 (2*OPH)
#define SMEM1 (NSTAGE*STG1*2)       // 61440 bytes

__global__ void __launch_bounds__(256)
gemm_lm(const __half* __restrict__ A, const __half* __restrict__ Bm,
        float* __restrict__ C, int N)
{
    int bm = blockIdx.x, bn = blockIdx.y;   // bm fastest -> wte tile reuse in L2
    const int K = EE, KT = K / BK;

    extern __shared__ __half sm2[];
    uint32_t smb = (uint32_t)__cvta_generic_to_shared(sm2);

    int tid = threadIdx.x;
    const __half* Ab = A  + (long)bm*BM*K;
    const __half* Bb = Bm + (long)bn*BN*K;
    int nbase = bn*BN;

    int seg = tid & 3;
    int row0 = tid >> 2, row1 = (tid + 256) >> 2;

    auto load_stage = [&](int s, int kt){
        int k0 = kt*BK;
        uint32_t base = smb + (uint32_t)s*STG1*2;
        #pragma unroll
        for (int c = 0; c < 2; c++){
            int row = c ? row1 : row0;
            uint32_t so = (uint32_t)(row*RS + seg*8)*2;
            cpa16(base + so, Ab + (long)row*K + k0 + seg*8, 16);
            int bsz = (nbase + row < N) ? 16 : 0;
            cpa16(base + OPH*2 + so, Bb + (long)row*K + k0 + seg*8, bsz);
        }
    };

    load_stage(0, 0);
    asm volatile("cp.async.commit_group;\n");
    load_stage(1, 1);
    asm volatile("cp.async.commit_group;\n");

    float c[4][4][4];
    #pragma unroll
    for (int i=0;i<4;i++)
        #pragma unroll
        for (int j=0;j<4;j++){ c[i][j][0]=0.f;c[i][j][1]=0.f;c[i][j][2]=0.f;c[i][j][3]=0.f; }

    int lane = tid & 31, wid = tid >> 5;
    int wm = (wid >> 2) * 64;
    int wn = (wid & 3) * 32;
    int gq = lane >> 2, tg = lane & 3;
    int aR = lane & 15,        aC = (lane >> 4) * 8;
    int bR = lane & 7,         bC = ((lane >> 3) & 1) * 8;

    for (int kt = 0; kt < KT; kt++){
        __syncthreads();
        if (kt + 2 < KT) load_stage((kt+2)%NSTAGE, kt+2);
        asm volatile("cp.async.commit_group;\n");
        asm volatile("cp.async.wait_group 1;\n");
        __syncthreads();

        uint32_t base = smb + (uint32_t)(kt % NSTAGE)*STG1*2;
        uint32_t baseA = base, baseB = base + OPH*2;

        #pragma unroll
        for (int ks = 0; ks < 2; ks++){
            int kc0 = ks*16;
            uint32_t af[4][4], bh[4][2];
            #pragma unroll
            for (int i=0;i<4;i++)
                ldsm4(af[i][0],af[i][1],af[i][2],af[i][3],
                      baseA + (uint32_t)((wm + i*16 + aR)*RS + kc0 + aC)*2);
            #pragma unroll
            for (int j=0;j<4;j++)
                ldsm2(bh[j][0],bh[j][1],
                      baseB + (uint32_t)((wn + j*8 + bR)*RS + kc0 + bC)*2);
            #pragma unroll
            for (int i=0;i<4;i++)
                #pragma unroll
                for (int j=0;j<4;j++)
                    MMA_F16(c[i][j], af[i][0],af[i][1],af[i][2],af[i][3], bh[j][0],bh[j][1]);
        }
    }

    #pragma unroll
    for (int i=0;i<4;i++){
        int r0 = bm*BM + wm + i*16 + gq;
        #pragma unroll
        for (int j=0;j<4;j++){
            int c0 = nbase + wn + j*8 + tg*2;
            #pragma unroll
            for (int h2=0; h2<2; h2++){
                long rb = (long)(r0 + h2*8)*VV;
                #pragma unroll
                for (int cc=0; cc<2; cc++){
                    int col = c0 + cc;
                    if (col < N) C[rb + col] = c[i][j][h2*2 + cc];
                }
            }
        }
    }
}

// ---------------- embedding ----------------
__global__ void embed_k(const int* __restrict__ idx, const float* __restrict__ wte,
                        const float* __restrict__ wpe, float* __restrict__ x)
{
    int i = blockIdx.x*256 + threadIdx.x;
    if (i >= NROWS*EE) return;
    int row = i / EE, col = i - row*EE;
    int t = row & (TT-1);
    x[i] = wte[(long)idx[row]*EE + col] + wpe[(long)t*EE + col];
}

// ---------------- layernorm -> fp16 ----------------
__global__ void layernorm_f16(const float* __restrict__ x, const float* __restrict__ w,
                              const float* __restrict__ b, __half* __restrict__ o)
{
    int row = blockIdx.x;
    const float* xr = x + (long)row*EE;
    long obase = (long)row*EE;
    int tid = threadIdx.x;
    float v0 = xr[tid], v1 = xr[tid+256], v2 = xr[tid+512];
    float s = v0+v1+v2, q = v0*v0+v1*v1+v2*v2;
    __shared__ float sh1[256], sh2[256];
    sh1[tid]=s; sh2[tid]=q; __syncthreads();
    #pragma unroll
    for (int off=128; off>0; off>>=1){
        if (tid < off){ sh1[tid]+=sh1[tid+off]; sh2[tid]+=sh2[tid+off]; }
        __syncthreads();
    }
    float mean = sh1[0]*(1.f/EE);
    float var  = sh2[0]*(1.f/EE) - mean*mean;
    float rstd = rsqrtf(var + 1e-5f);
    #pragma unroll
    for (int p = 0; p < 3; p++){
        int cidx = tid + p*256;
        float vv = (p==0? v0 : p==1? v1 : v2);
        o[obase+cidx] = __float2half_rn((vv-mean)*rstd*w[cidx] + b[cidx]);
    }
}

// ---------------- V transpose (hi & lo, fp16) ----------------
__global__ void transpose_v(const __half* __restrict__ qh, const __half* __restrict__ ql,
                            __half* __restrict__ vh, __half* __restrict__ vl)
{
    int z = blockIdx.y; int b = z/HH, h = z - b*HH;
    int k0 = blockIdx.x * 64;
    __shared__ __half th[64][72], tl[64][72];
    const long sbase = ((long)(b*TT + k0))*(3*EE) + 2*EE + h*HDIM;
    int tid = threadIdx.x;
    #pragma unroll
    for (int i=0;i<16;i++){
        int id = tid + i*256;
        int kr = id >> 6, d = id & 63;
        th[kr][d] = qh[sbase + (long)kr*(3*EE) + d];
        tl[kr][d] = ql[sbase + (long)kr*(3*EE) + d];
    }
    __syncthreads();
    long dbase = (long)z*HDIM*TT + k0;
    #pragma unroll
    for (int i=0;i<16;i++){
        int id = tid + i*256;
        int d = id >> 6, kc = id & 63;
        vh[dbase + (long)d*TT + kc] = th[kc][d];
        vl[dbase + (long)d*TT + kc] = tl[kc][d];
    }
}

// ---------------- causal row softmax -> fp16 probs ----------------
__global__ void softmax_causal(const float* __restrict__ att, __half* __restrict__ pf)
{
    int rid = blockIdx.x;
    int z = rid >> 10, q = rid & (TT-1);
    long base = (long)z*TT*TT + (long)q*TT;
    const float* p = att + base;
    int kend = ((q >> 7) + 1) << 7;
    int tid = threadIdx.x;
    float v[4];
    float m = -1e30f;
    #pragma unroll
    for (int i=0;i<4;i++){
        int k = tid + i*256;
        v[i] = (k < kend) ? p[k] : -1e30f;
        m = fmaxf(m, v[i]);
    }
    __shared__ float sh[256];
    sh[tid] = m; __syncthreads();
    #pragma unroll
    for (int off=128; off>0; off>>=1){
        if (tid < off) sh[tid] = fmaxf(sh[tid], sh[tid+off]);
        __syncthreads();
    }
    m = sh[0]; __syncthreads();
    float s = 0.f;
    #pragma unroll
    for (int i=0;i<4;i++){ v[i] = __expf(v[i] - m); s += v[i]; }
    sh[tid] = s; __syncthreads();
    #pragma unroll
    for (int off=128; off>0; off>>=1){
        if (tid < off) sh[tid] += sh[tid+off];
        __syncthreads();
    }
    float inv = 1.f / sh[0];
    #pragma unroll
    for (int i=0;i<4;i++){
        int k = tid + i*256;
        if (k < kend) pf[base+k] = __float2half_rn(v[i]*inv);
    }
}

// ---------------- loss ----------------
__global__ void loss_rows(const float* __restrict__ lg, const int* __restrict__ tgt,
                          float* __restrict__ nll, float* __restrict__ vld)
{
    long row = blockIdx.x;
    const float* p = lg + row*(long)VV;
    int tid = threadIdx.x;
    float m = -3.0e38f, s = 0.f;
    for (int k = tid; k < VV; k += 256){
        float x = p[k];
        if (x > m){ s = s*__expf(m - x) + 1.f; m = x; }
        else s += __expf(x - m);
    }
    __shared__ float sm[256], ss[256];
    sm[tid]=m; ss[tid]=s; __syncthreads();
    #pragma unroll
    for (int off=128; off>0; off>>=1){
        if (tid < off){
            float m2 = sm[tid+off], s2 = ss[tid+off];
            float mm = fmaxf(sm[tid], m2);
            ss[tid] = ss[tid]*__expf(sm[tid]-mm) + s2*__expf(m2-mm);
            sm[tid] = mm;
        }
        __syncthreads();
    }
    if (tid == 0){
        float lse = sm[0] + logf(ss[0]);
        int t = tgt[row];
        if (t != -1){ nll[row] = lse - p[t]; vld[row] = 1.f; }
        else        { nll[row] = 0.f;       vld[row] = 0.f; }
    }
}

__global__ void loss_final(const float* __restrict__ nll, const float* __restrict__ vld,
                           float* __restrict__ out)
{
    int tid = threadIdx.x;
    float a = 0.f, b = 0.f;
    for (int i = tid; i < NROWS; i += 256){ a += nll[i]; b += vld[i]; }
    __shared__ float s1[256], s2[256];
    s1[tid]=a; s2[tid]=b; __syncthreads();
    #pragma unroll
    for (int off=128; off>0; off>>=1){
        if (tid < off){ s1[tid]+=s1[tid+off]; s2[tid]+=s2[tid+off]; }
        __syncthreads();
    }
    if (tid == 0) out[0] = s1[0] / fmaxf(s2[0], 1.f);
}

// ---------------- host ----------------
static void splitf_arr(const float* src, __half* h, __half* l, long n){
    int n4 = (int)(n/4);
    splitf4_k<<<(n4 + 255)/256, 256>>>((const float4*)src, (uint32_t*)h, (uint32_t*)l, n4);
}

extern "C" void kernel_launch(void* const* d_in, const int* in_sizes, int n_in,
                              void* d_out, int out_size)
{
    const int*   idx     = (const int*)  d_in[0];
    const int*   tgt     = (const int*)  d_in[1];
    const float* wte     = (const float*)d_in[2];
    const float* wpe     = (const float*)d_in[3];
    const float* ln1_w   = (const float*)d_in[4];
    const float* ln1_b   = (const float*)d_in[5];
    const float* attn_w  = (const float*)d_in[6];
    const float* attn_b  = (const float*)d_in[7];
    const float* aproj_w = (const float*)d_in[8];
    const float* aproj_b = (const float*)d_in[9];
    const float* ln2_w   = (const float*)d_in[10];
    const float* ln2_b   = (const float*)d_in[11];
    const float* fc_w    = (const float*)d_in[12];
    const float* fc_b    = (const float*)d_in[13];
    const float* proj_w  = (const float*)d_in[14];
    const float* proj_b  = (const float*)d_in[15];
    const float* lnf_w   = (const float*)d_in[16];
    const float* lnf_b   = (const float*)d_in[17];
    float* out = (float*)d_out;

    float *x, *att, *nll, *vld;
    __half *xn_f,*qkv_h,*qkv_l,*p_f,*vT_h,*vT_l,*y_f,*h_f;
    __half *wte_f,*aw_h,*aw_l,*pw_h,*pw_l,*fw_h,*fw_l,*mw_h,*mw_l;
    cudaGetSymbolAddress((void**)&x,    g_x);
    cudaGetSymbolAddress((void**)&att,  g_att);
    cudaGetSymbolAddress((void**)&nll,  g_nll);
    cudaGetSymbolAddress((void**)&vld,  g_vld);
    cudaGetSymbolAddress((void**)&xn_f, g_xn_f);
    cudaGetSymbolAddress((void**)&qkv_h,g_qkv_h); cudaGetSymbolAddress((void**)&qkv_l,g_qkv_l);
    cudaGetSymbolAddress((void**)&p_f,  g_p_f);
    cudaGetSymbolAddress((void**)&vT_h, g_vT_h);  cudaGetSymbolAddress((void**)&vT_l, g_vT_l);
    cudaGetSymbolAddress((void**)&y_f,  g_y_f);
    cudaGetSymbolAddress((void**)&h_f,  g_h_f);
    cudaGetSymbolAddress((void**)&wte_f,g_wte_f);
    cudaGetSymbolAddress((void**)&aw_h, g_aw_h);  cudaGetSymbolAddress((void**)&aw_l, g_aw_l);
    cudaGetSymbolAddress((void**)&pw_h, g_pw_h);  cudaGetSymbolAddress((void**)&pw_l, g_pw_l);
    cudaGetSymbolAddress((void**)&fw_h, g_fw_h);  cudaGetSymbolAddress((void**)&fw_l, g_fw_l);
    cudaGetSymbolAddress((void**)&mw_h, g_mw_h);  cudaGetSymbolAddress((void**)&mw_l, g_mw_l);

    cudaFuncSetAttribute(gemm_f2<0>, cudaFuncAttributeMaxDynamicSharedMemorySize, SMEM3);
    cudaFuncSetAttribute(gemm_f2<1>, cudaFuncAttributeMaxDynamicSharedMemorySize, SMEM3);
    cudaFuncSetAttribute(gemm_f2<2>, cudaFuncAttributeMaxDynamicSharedMemorySize, SMEM3);
    cudaFuncSetAttribute(gemm_f2<3>, cudaFuncAttributeMaxDynamicSharedMemorySize, SMEM3);
    cudaFuncSetAttribute(gemm_f2<4>, cudaFuncAttributeMaxDynamicSharedMemorySize, SMEM3);
    cudaFuncSetAttribute(gemm_lm,    cudaFuncAttributeMaxDynamicSharedMemorySize, SMEM1);

    // one-shot weight preprocessing (fp16 hi/lo; wte single fp16)
    splitf_arr(attn_w,  aw_h, aw_l, (long)LL*3*EE*EE);
    splitf_arr(aproj_w, pw_h, pw_l, (long)LL*EE*EE);
    splitf_arr(fc_w,    fw_h, fw_l, (long)LL*4*EE*EE);
    splitf_arr(proj_w,  mw_h, mw_l, (long)LL*4*EE*EE);
    {
        long n4 = (long)VV*EE/4;
        tohalf4_k<<<(int)((n4 + 255)/256), 256>>>((const float4*)wte, (__half2*)wte_f, (int)n4);
    }

    embed_k<<<(NROWS*EE + 255)/256, 256>>>(idx, wte, wpe, x);

    for (int l = 0; l < LL; l++){
        layernorm_f16<<<NROWS, 256>>>(x, ln1_w + l*EE, ln1_b + l*EE, xn_f);

        // QKV = xn @ attn_w^T + b  -> hi/lo fp16
        gemm_f2<0><<<dim3(3*EE/BN, NROWS/BM, 1), 256, SMEM3>>>(
            xn_f, 0, 0, EE,
            aw_h + (long)l*3*EE*EE, aw_l + (long)l*3*EE*EE, 0, 0, EE,
            nullptr, qkv_h, qkv_l, 0, 0, 3*EE,
            attn_b + (long)l*3*EE, nullptr, 0,
            NROWS, 3*EE, EE, 1, 1.f);

        transpose_v<<<dim3(TT/64, BB*HH), 256>>>(qkv_h, qkv_l, vT_h, vT_l);

        // scores = Q K^T / 8 (A = Q single = qkv_h, B = K split; causal, z=48)
        gemm_f2<3><<<dim3(TT/BN, TT/BM, BB*HH), 256, SMEM3>>>(
            qkv_h,      (long)TT*3*EE, HDIM, 3*EE,
            qkv_h + EE, qkv_l + EE, (long)TT*3*EE, HDIM, 3*EE,
            att, nullptr, nullptr, (long)HH*TT*TT, (long)TT*TT, TT,
            nullptr, nullptr, 0,
            TT, TT, HDIM, HH, 0.125f);

        softmax_causal<<<BB*HH*TT, 256>>>(att, p_f);

        // y = P @ V  (A = probs single, B = V split; K trimmed)
        gemm_f2<4><<<dim3(1, TT/BM, BB*HH), 256, SMEM3>>>(
            p_f, (long)HH*TT*TT, (long)TT*TT, TT,
            vT_h, vT_l, (long)HH*HDIM*TT, (long)HDIM*TT, TT,
            nullptr, y_f, nullptr, (long)TT*EE, HDIM, EE,
            nullptr, nullptr, 0,
            TT, HDIM, TT, HH, 1.f);

        // x += y @ aproj^T + b
        gemm_f2<2><<<dim3(EE/BN, NROWS/BM, 1), 256, SMEM3>>>(
            y_f, 0, 0, EE,
            pw_h + (long)l*EE*EE, pw_l + (long)l*EE*EE, 0, 0, EE,
            x, nullptr, nullptr, 0, 0, EE,
            aproj_b + (long)l*EE, x, EE,
            NROWS, EE, EE, 1, 1.f);

        layernorm_f16<<<NROWS, 256>>>(x, ln2_w + l*EE, ln2_b + l*EE, xn_f);

        // h = gelu(xn @ fc^T + b) -> single fp16
        gemm_f2<1><<<dim3(4*EE/BN, NROWS/BM, 1), 256, SMEM3>>>(
            xn_f, 0, 0, EE,
            fw_h + (long)l*4*EE*EE, fw_l + (long)l*4*EE*EE, 0, 0, EE,
            nullptr, h_f, nullptr, 0, 0, 4*EE,
            fc_b + (long)l*4*EE, nullptr, 0,
            NROWS, 4*EE, EE, 1, 1.f);

        // x += h @ proj^T + b
        gemm_f2<2><<<dim3(EE/BN, NROWS/BM, 1), 256, SMEM3>>>(
            h_f, 0, 0, 4*EE,
            mw_h + (long)l*4*EE*EE, mw_l + (long)l*4*EE*EE, 0, 0, 4*EE,
            x, nullptr, nullptr, 0, 0, EE,
            proj_b + (long)l*EE, x, EE,
            NROWS, EE, 4*EE, 1, 1.f);
    }

    layernorm_f16<<<NROWS, 256>>>(x, lnf_w, lnf_b, xn_f);

    // logits = xn @ wte^T (fp16 single-pass) -> d_out
    gemm_lm<<<dim3(NROWS/BM, (VV + BN - 1)/BN, 1), 256, SMEM1>>>(
        xn_f, wte_f, out, VV);

    long BTV = (long)NROWS * VV;
    if ((long)out_size > BTV){
        loss_rows<<<NROWS, 256>>>(out, tgt, nll, vld);
        loss_final<<<1, 256>>>(nll, vld, out + BTV);
    }
}

// round 15
// speedup vs baseline: 2.5228x; 1.2580x over previous
#include <cuda_runtime.h>
#include <cuda_fp16.h>
#include <cstdint>
#include <math.h>

// ---------------- problem constants ----------------
#define BB 4
#define TT 1024
#define EE 768
#define HH 12
#define LL 4
#define VV 50257
#define HDIM 64
#define NROWS (BB*TT)          // 4096

// ---------------- scratch (device globals) ----------------
__device__ float g_x  [NROWS*EE];
__device__ float g_att[(size_t)BB*HH*TT*TT];
__device__ float g_nll[NROWS];
__device__ float g_vld[NROWS];

__device__ __half g_xn_f [NROWS*EE];                 // LN out
__device__ __half g_qkv_f[NROWS*3*EE];               // QKV
__device__ __half g_p_f  [(size_t)BB*HH*TT*TT];      // softmax probs
__device__ __half g_vT_f [(size_t)BB*HH*HDIM*TT];    // V transposed
__device__ __half g_y_f  [NROWS*EE];                 // AV out
__device__ __half g_h_f  [NROWS*4*EE];               // fc out

__device__ __half g_wte_f[(size_t)VV*EE];
__device__ __half g_aw_f [LL*3*EE*EE];
__device__ __half g_pw_f [LL*EE*EE];
__device__ __half g_fw_f [LL*4*EE*EE];
__device__ __half g_mw_f [LL*4*EE*EE];

// ---------------- helpers ----------------
__global__ void tohalf4_k(const float4* __restrict__ in, __half2* __restrict__ o, int n4)
{
    int i = blockIdx.x*256 + threadIdx.x;
    if (i >= n4) return;
    float4 v = in[i];
    o[2*i]   = __floats2half2_rn(v.x, v.y);
    o[2*i+1] = __floats2half2_rn(v.z, v.w);
}

// ---------------- common GEMM machinery (proven skeleton) ----------------
#define BM 128
#define BN 128
#define BK 32
#define RS 40                   // halves per smem row (80B) -> conflict-free ldmatrix
#define OPH (128*RS)            // halves per operand per stage
#define NSTAGE 3
#define STG1 (2*OPH)            // A + B
#define SMEM1 (NSTAGE*STG1*2)   // 61440 bytes

__device__ __forceinline__ void cpa16(uint32_t dst, const void* src, int sz){
    asm volatile("cp.async.cg.shared.global [%0], [%1], 16, %2;\n"
                 :: "r"(dst), "l"(src), "r"(sz));
}
__device__ __forceinline__ void ldsm4(uint32_t& r0, uint32_t& r1, uint32_t& r2,
                                      uint32_t& r3, uint32_t a){
    asm volatile("ldmatrix.sync.aligned.m8n8.x4.shared.b16 {%0,%1,%2,%3}, [%4];\n"
                 : "=r"(r0),"=r"(r1),"=r"(r2),"=r"(r3) : "r"(a));
}
__device__ __forceinline__ void ldsm2(uint32_t& r0, uint32_t& r1, uint32_t a){
    asm volatile("ldmatrix.sync.aligned.m8n8.x2.shared.b16 {%0,%1}, [%2];\n"
                 : "=r"(r0),"=r"(r1) : "r"(a));
}
#define MMA_F16(Cc, A0,A1,A2,A3, B0,B1)                                      \
    asm volatile("mma.sync.aligned.m16n8k16.row.col.f32.f16.f16.f32 "        \
        "{%0,%1,%2,%3}, {%4,%5,%6,%7}, {%8,%9}, {%0,%1,%2,%3};\n"            \
        : "+f"(Cc[0]), "+f"(Cc[1]), "+f"(Cc[2]), "+f"(Cc[3])                 \
        : "r"(A0), "r"(A1), "r"(A2), "r"(A3), "r"(B0), "r"(B1));

// ---------------- layer GEMM: single-pass fp16 ----------------
// NT: A[M,K] K-major, B[N,K] K-major, C = A*B^T
// MODE: 0 = +bias -> fp16 (QKV)        1 = +bias, GELU -> fp16 (fc)
//       2 = +bias+residual -> f32      3 = *scale, causal mask -> f32 (skip upper)
//       4 = -> fp16, K trimmed (AV)
template<int MODE>
__global__ void __launch_bounds__(256)
gemm_f1(const __half* __restrict__ A, long sAo, long sAi, int lda,
        const __half* __restrict__ B, long sBo, long sBi, int ldb,
        float* __restrict__ Cf, __half* __restrict__ Ch,
        long sCo, long sCi, int ldc,
        const float* __restrict__ bias, const float* __restrict__ Res, int ldr,
        int M, int N, int K, int innerCnt, float scale)
{
    int bn = blockIdx.x, bm = blockIdx.y, bz = blockIdx.z;
    if (MODE == 3 && bn > bm) return;       // causal: block above diagonal
    int zo = bz / innerCnt, zi = bz - zo*innerCnt;
    long ao = zo*sAo + zi*sAi, bo = zo*sBo + zi*sBi, co = zo*sCo + zi*sCi;

    extern __shared__ __half sm[];
    uint32_t smb = (uint32_t)__cvta_generic_to_shared(sm);

    int Keff = (MODE == 4) ? min(K, (bm+1)*BM) : K;
    int KT = Keff / BK;

    int tid = threadIdx.x;
    const __half* Ab = A + ao + (long)bm*BM*lda;
    const __half* Bb = B + bo + (long)bn*BN*ldb;
    int nbase = bn*BN;

    int seg = tid & 3;
    int row0 = tid >> 2, row1 = (tid + 256) >> 2;

    auto load_stage = [&](int s, int kt){
        int k0 = kt*BK;
        uint32_t base = smb + (uint32_t)s*STG1*2;
        #pragma unroll
        for (int c = 0; c < 2; c++){
            int row = c ? row1 : row0;
            uint32_t so = (uint32_t)(row*RS + seg*8)*2;
            cpa16(base + so, Ab + (long)row*lda + k0 + seg*8, 16);
            int bsz = (nbase + row < N) ? 16 : 0;
            cpa16(base + OPH*2 + so, Bb + (long)row*ldb + k0 + seg*8, bsz);
        }
    };

    load_stage(0, 0);
    asm volatile("cp.async.commit_group;\n");
    load_stage(1, 1);
    asm volatile("cp.async.commit_group;\n");

    float c[4][4][4];
    #pragma unroll
    for (int i=0;i<4;i++)
        #pragma unroll
        for (int j=0;j<4;j++){ c[i][j][0]=0.f;c[i][j][1]=0.f;c[i][j][2]=0.f;c[i][j][3]=0.f; }

    int lane = tid & 31, wid = tid >> 5;
    int wm = (wid >> 2) * 64;
    int wn = (wid & 3) * 32;
    int gq = lane >> 2, tg = lane & 3;
    int aR = lane & 15,        aC = (lane >> 4) * 8;
    int bR = lane & 7,         bC = ((lane >> 3) & 1) * 8;

    for (int kt = 0; kt < KT; kt++){
        __syncthreads();
        if (kt + 2 < KT) load_stage((kt+2)%NSTAGE, kt+2);
        asm volatile("cp.async.commit_group;\n");
        asm volatile("cp.async.wait_group 1;\n");
        __syncthreads();

        uint32_t base  = smb + (uint32_t)(kt % NSTAGE)*STG1*2;
        uint32_t baseA = base, baseB = base + OPH*2;

        #pragma unroll
        for (int ks = 0; ks < 2; ks++){
            int kc0 = ks*16;
            uint32_t af[4][4], bf[4][2];
            #pragma unroll
            for (int i=0;i<4;i++)
                ldsm4(af[i][0],af[i][1],af[i][2],af[i][3],
                      baseA + (uint32_t)((wm + i*16 + aR)*RS + kc0 + aC)*2);
            #pragma unroll
            for (int j=0;j<4;j++)
                ldsm2(bf[j][0],bf[j][1],
                      baseB + (uint32_t)((wn + j*8 + bR)*RS + kc0 + bC)*2);
            #pragma unroll
            for (int i=0;i<4;i++)
                #pragma unroll
                for (int j=0;j<4;j++)
                    MMA_F16(c[i][j], af[i][0],af[i][1],af[i][2],af[i][3], bf[j][0],bf[j][1]);
        }
    }

    #pragma unroll
    for (int i=0;i<4;i++){
        int r0 = bm*BM + wm + i*16 + gq;
        #pragma unroll
        for (int j=0;j<4;j++){
            int c0 = nbase + wn + j*8 + tg*2;
            #pragma unroll
            for (int h2=0; h2<2; h2++){
                int rr = r0 + h2*8;
                #pragma unroll
                for (int cc=0; cc<2; cc++){
                    int col = c0 + cc;
                    if (col >= N) continue;
                    float v = c[i][j][h2*2 + cc];
                    long oidx = co + (long)rr*ldc + col;
                    if (MODE == 0){
                        Ch[oidx] = __float2half_rn(v + bias[col]);
                    } else if (MODE == 1){
                        v += bias[col];
                        v = 0.5f*v*(1.f + erff(v*0.70710678118654752f));
                        Ch[oidx] = __float2half_rn(v);
                    } else if (MODE == 2){
                        Cf[oidx] = v + bias[col] + Res[(long)rr*ldr + col];
                    } else if (MODE == 3){
                        v *= scale; if (col > rr) v = -1e30f;
                        Cf[oidx] = v;
                    } else if (MODE == 4){
                        Ch[oidx] = __float2half_rn(v);
                    }
                }
            }
        }
    }
}

// ---------------- lm-head GEMM (bm-fastest grid for wte L2 reuse) ------------
__global__ void __launch_bounds__(256)
gemm_lm(const __half* __restrict__ A, const __half* __restrict__ Bm,
        float* __restrict__ C, int N)
{
    int bm = blockIdx.x, bn = blockIdx.y;
    const int K = EE, KT = K / BK;

    extern __shared__ __half sm2[];
    uint32_t smb = (uint32_t)__cvta_generic_to_shared(sm2);

    int tid = threadIdx.x;
    const __half* Ab = A  + (long)bm*BM*K;
    const __half* Bb = Bm + (long)bn*BN*K;
    int nbase = bn*BN;

    int seg = tid & 3;
    int row0 = tid >> 2, row1 = (tid + 256) >> 2;

    auto load_stage = [&](int s, int kt){
        int k0 = kt*BK;
        uint32_t base = smb + (uint32_t)s*STG1*2;
        #pragma unroll
        for (int c = 0; c < 2; c++){
            int row = c ? row1 : row0;
            uint32_t so = (uint32_t)(row*RS + seg*8)*2;
            cpa16(base + so, Ab + (long)row*K + k0 + seg*8, 16);
            int bsz = (nbase + row < N) ? 16 : 0;
            cpa16(base + OPH*2 + so, Bb + (long)row*K + k0 + seg*8, bsz);
        }
    };

    load_stage(0, 0);
    asm volatile("cp.async.commit_group;\n");
    load_stage(1, 1);
    asm volatile("cp.async.commit_group;\n");

    float c[4][4][4];
    #pragma unroll
    for (int i=0;i<4;i++)
        #pragma unroll
        for (int j=0;j<4;j++){ c[i][j][0]=0.f;c[i][j][1]=0.f;c[i][j][2]=0.f;c[i][j][3]=0.f; }

    int lane = tid & 31, wid = tid >> 5;
    int wm = (wid >> 2) * 64;
    int wn = (wid & 3) * 32;
    int gq = lane >> 2, tg = lane & 3;
    int aR = lane & 15,        aC = (lane >> 4) * 8;
    int bR = lane & 7,         bC = ((lane >> 3) & 1) * 8;

    for (int kt = 0; kt < KT; kt++){
        __syncthreads();
        if (kt + 2 < KT) load_stage((kt+2)%NSTAGE, kt+2);
        asm volatile("cp.async.commit_group;\n");
        asm volatile("cp.async.wait_group 1;\n");
        __syncthreads();

        uint32_t base = smb + (uint32_t)(kt % NSTAGE)*STG1*2;
        uint32_t baseA = base, baseB = base + OPH*2;

        #pragma unroll
        for (int ks = 0; ks < 2; ks++){
            int kc0 = ks*16;
            uint32_t af[4][4], bf[4][2];
            #pragma unroll
            for (int i=0;i<4;i++)
                ldsm4(af[i][0],af[i][1],af[i][2],af[i][3],
                      baseA + (uint32_t)((wm + i*16 + aR)*RS + kc0 + aC)*2);
            #pragma unroll
            for (int j=0;j<4;j++)
                ldsm2(bf[j][0],bf[j][1],
                      baseB + (uint32_t)((wn + j*8 + bR)*RS + kc0 + bC)*2);
            #pragma unroll
            for (int i=0;i<4;i++)
                #pragma unroll
                for (int j=0;j<4;j++)
                    MMA_F16(c[i][j], af[i][0],af[i][1],af[i][2],af[i][3], bf[j][0],bf[j][1]);
        }
    }

    #pragma unroll
    for (int i=0;i<4;i++){
        int r0 = bm*BM + wm + i*16 + gq;
        #pragma unroll
        for (int j=0;j<4;j++){
            int c0 = nbase + wn + j*8 + tg*2;
            #pragma unroll
            for (int h2=0; h2<2; h2++){
                long rb = (long)(r0 + h2*8)*VV;
                #pragma unroll
                for (int cc=0; cc<2; cc++){
                    int col = c0 + cc;
                    if (col < N) C[rb + col] = c[i][j][h2*2 + cc];
                }
            }
        }
    }
}

// ---------------- embedding ----------------
__global__ void embed_k(const int* __restrict__ idx, const float* __restrict__ wte,
                        const float* __restrict__ wpe, float* __restrict__ x)
{
    int i = blockIdx.x*256 + threadIdx.x;
    if (i >= NROWS*EE) return;
    int row = i / EE, col = i - row*EE;
    int t = row & (TT-1);
    x[i] = wte[(long)idx[row]*EE + col] + wpe[(long)t*EE + col];
}

// ---------------- layernorm -> fp16 ----------------
__global__ void layernorm_f16(const float* __restrict__ x, const float* __restrict__ w,
                              const float* __restrict__ b, __half* __restrict__ o)
{
    int row = blockIdx.x;
    const float* xr = x + (long)row*EE;
    long obase = (long)row*EE;
    int tid = threadIdx.x;
    float v0 = xr[tid], v1 = xr[tid+256], v2 = xr[tid+512];
    float s = v0+v1+v2, q = v0*v0+v1*v1+v2*v2;
    __shared__ float sh1[256], sh2[256];
    sh1[tid]=s; sh2[tid]=q; __syncthreads();
    #pragma unroll
    for (int off=128; off>0; off>>=1){
        if (tid < off){ sh1[tid]+=sh1[tid+off]; sh2[tid]+=sh2[tid+off]; }
        __syncthreads();
    }
    float mean = sh1[0]*(1.f/EE);
    float var  = sh2[0]*(1.f/EE) - mean*mean;
    float rstd = rsqrtf(var + 1e-5f);
    #pragma unroll
    for (int p = 0; p < 3; p++){
        int cidx = tid + p*256;
        float vv = (p==0? v0 : p==1? v1 : v2);
        o[obase+cidx] = __float2half_rn((vv-mean)*rstd*w[cidx] + b[cidx]);
    }
}

// ---------------- V transpose (fp16) ----------------
__global__ void transpose_v(const __half* __restrict__ q, __half* __restrict__ v)
{
    int z = blockIdx.y; int b = z/HH, h = z - b*HH;
    int k0 = blockIdx.x * 64;
    __shared__ __half t[64][72];
    const long sbase = ((long)(b*TT + k0))*(3*EE) + 2*EE + h*HDIM;
    int tid = threadIdx.x;
    #pragma unroll
    for (int i=0;i<16;i++){
        int id = tid + i*256;
        int kr = id >> 6, d = id & 63;
        t[kr][d] = q[sbase + (long)kr*(3*EE) + d];
    }
    __syncthreads();
    long dbase = (long)z*HDIM*TT + k0;
    #pragma unroll
    for (int i=0;i<16;i++){
        int id = tid + i*256;
        int d = id >> 6, kc = id & 63;
        v[dbase + (long)d*TT + kc] = t[kc][d];
    }
}

// ---------------- causal row softmax -> fp16 probs ----------------
__global__ void softmax_causal(const float* __restrict__ att, __half* __restrict__ pf)
{
    int rid = blockIdx.x;
    int z = rid >> 10, q = rid & (TT-1);
    long base = (long)z*TT*TT + (long)q*TT;
    const float* p = att + base;
    int kend = ((q >> 7) + 1) << 7;
    int tid = threadIdx.x;
    float v[4];
    float m = -1e30f;
    #pragma unroll
    for (int i=0;i<4;i++){
        int k = tid + i*256;
        v[i] = (k < kend) ? p[k] : -1e30f;
        m = fmaxf(m, v[i]);
    }
    __shared__ float sh[256];
    sh[tid] = m; __syncthreads();
    #pragma unroll
    for (int off=128; off>0; off>>=1){
        if (tid < off) sh[tid] = fmaxf(sh[tid], sh[tid+off]);
        __syncthreads();
    }
    m = sh[0]; __syncthreads();
    float s = 0.f;
    #pragma unroll
    for (int i=0;i<4;i++){ v[i] = __expf(v[i] - m); s += v[i]; }
    sh[tid] = s; __syncthreads();
    #pragma unroll
    for (int off=128; off>0; off>>=1){
        if (tid < off) sh[tid] += sh[tid+off];
        __syncthreads();
    }
    float inv = 1.f / sh[0];
    #pragma unroll
    for (int i=0;i<4;i++){
        int k = tid + i*256;
        if (k < kend) pf[base+k] = __float2half_rn(v[i]*inv);
    }
}

// ---------------- loss ----------------
__global__ void loss_rows(const float* __restrict__ lg, const int* __restrict__ tgt,
                          float* __restrict__ nll, float* __restrict__ vld)
{
    long row = blockIdx.x;
    const float* p = lg + row*(long)VV;
    int tid = threadIdx.x;
    float m = -3.0e38f, s = 0.f;
    for (int k = tid; k < VV; k += 256){
        float x = p[k];
        if (x > m){ s = s*__expf(m - x) + 1.f; m = x; }
        else s += __expf(x - m);
    }
    __shared__ float sm[256], ss[256];
    sm[tid]=m; ss[tid]=s; __syncthreads();
    #pragma unroll
    for (int off=128; off>0; off>>=1){
        if (tid < off){
            float m2 = sm[tid+off], s2 = ss[tid+off];
            float mm = fmaxf(sm[tid], m2);
            ss[tid] = ss[tid]*__expf(sm[tid]-mm) + s2*__expf(m2-mm);
            sm[tid] = mm;
        }
        __syncthreads();
    }
    if (tid == 0){
        float lse = sm[0] + logf(ss[0]);
        int t = tgt[row];
        if (t != -1){ nll[row] = lse - p[t]; vld[row] = 1.f; }
        else        { nll[row] = 0.f;       vld[row] = 0.f; }
    }
}

__global__ void loss_final(const float* __restrict__ nll, const float* __restrict__ vld,
                           float* __restrict__ out)
{
    int tid = threadIdx.x;
    float a = 0.f, b = 0.f;
    for (int i = tid; i < NROWS; i += 256){ a += nll[i]; b += vld[i]; }
    __shared__ float s1[256], s2[256];
    s1[tid]=a; s2[tid]=b; __syncthreads();
    #pragma unroll
    for (int off=128; off>0; off>>=1){
        if (tid < off){ s1[tid]+=s1[tid+off]; s2[tid]+=s2[tid+off]; }
        __syncthreads();
    }
    if (tid == 0) out[0] = s1[0] / fmaxf(s2[0], 1.f);
}

// ---------------- host ----------------
static void tohalf_arr(const float* src, __half* o, long n){
    int n4 = (int)(n/4);
    tohalf4_k<<<(n4 + 255)/256, 256>>>((const float4*)src, (__half2*)o, n4);
}

extern "C" void kernel_launch(void* const* d_in, const int* in_sizes, int n_in,
                              void* d_out, int out_size)
{
    const int*   idx     = (const int*)  d_in[0];
    const int*   tgt     = (const int*)  d_in[1];
    const float* wte     = (const float*)d_in[2];
    const float* wpe     = (const float*)d_in[3];
    const float* ln1_w   = (const float*)d_in[4];
    const float* ln1_b   = (const float*)d_in[5];
    const float* attn_w  = (const float*)d_in[6];
    const float* attn_b  = (const float*)d_in[7];
    const float* aproj_w = (const float*)d_in[8];
    const float* aproj_b = (const float*)d_in[9];
    const float* ln2_w   = (const float*)d_in[10];
    const float* ln2_b   = (const float*)d_in[11];
    const float* fc_w    = (const float*)d_in[12];
    const float* fc_b    = (const float*)d_in[13];
    const float* proj_w  = (const float*)d_in[14];
    const float* proj_b  = (const float*)d_in[15];
    const float* lnf_w   = (const float*)d_in[16];
    const float* lnf_b   = (const float*)d_in[17];
    float* out = (float*)d_out;

    float *x, *att, *nll, *vld;
    __half *xn_f,*qkv_f,*p_f,*vT_f,*y_f,*h_f;
    __half *wte_f,*aw_f,*pw_f,*fw_f,*mw_f;
    cudaGetSymbolAddress((void**)&x,    g_x);
    cudaGetSymbolAddress((void**)&att,  g_att);
    cudaGetSymbolAddress((void**)&nll,  g_nll);
    cudaGetSymbolAddress((void**)&vld,  g_vld);
    cudaGetSymbolAddress((void**)&xn_f, g_xn_f);
    cudaGetSymbolAddress((void**)&qkv_f,g_qkv_f);
    cudaGetSymbolAddress((void**)&p_f,  g_p_f);
    cudaGetSymbolAddress((void**)&vT_f, g_vT_f);
    cudaGetSymbolAddress((void**)&y_f,  g_y_f);
    cudaGetSymbolAddress((void**)&h_f,  g_h_f);
    cudaGetSymbolAddress((void**)&wte_f,g_wte_f);
    cudaGetSymbolAddress((void**)&aw_f, g_aw_f);
    cudaGetSymbolAddress((void**)&pw_f, g_pw_f);
    cudaGetSymbolAddress((void**)&fw_f, g_fw_f);
    cudaGetSymbolAddress((void**)&mw_f, g_mw_f);

    cudaFuncSetAttribute(gemm_f1<0>, cudaFuncAttributeMaxDynamicSharedMemorySize, SMEM1);
    cudaFuncSetAttribute(gemm_f1<1>, cudaFuncAttributeMaxDynamicSharedMemorySize, SMEM1);
    cudaFuncSetAttribute(gemm_f1<2>, cudaFuncAttributeMaxDynamicSharedMemorySize, SMEM1);
    cudaFuncSetAttribute(gemm_f1<3>, cudaFuncAttributeMaxDynamicSharedMemorySize, SMEM1);
    cudaFuncSetAttribute(gemm_f1<4>, cudaFuncAttributeMaxDynamicSharedMemorySize, SMEM1);
    cudaFuncSetAttribute(gemm_lm,    cudaFuncAttributeMaxDynamicSharedMemorySize, SMEM1);

    // one-shot weight fp16 conversion
    tohalf_arr(attn_w,  aw_f, (long)LL*3*EE*EE);
    tohalf_arr(aproj_w, pw_f, (long)LL*EE*EE);
    tohalf_arr(fc_w,    fw_f, (long)LL*4*EE*EE);
    tohalf_arr(proj_w,  mw_f, (long)LL*4*EE*EE);
    tohalf_arr(wte,     wte_f, (long)VV*EE);

    embed_k<<<(NROWS*EE + 255)/256, 256>>>(idx, wte, wpe, x);

    for (int l = 0; l < LL; l++){
        layernorm_f16<<<NROWS, 256>>>(x, ln1_w + l*EE, ln1_b + l*EE, xn_f);

        // QKV = xn @ attn_w^T + b -> fp16
        gemm_f1<0><<<dim3(3*EE/BN, NROWS/BM, 1), 256, SMEM1>>>(
            xn_f, 0, 0, EE,
            aw_f + (long)l*3*EE*EE, 0, 0, EE,
            nullptr, qkv_f, 0, 0, 3*EE,
            attn_b + (long)l*3*EE, nullptr, 0,
            NROWS, 3*EE, EE, 1, 1.f);

        transpose_v<<<dim3(TT/64, BB*HH), 256>>>(qkv_f, vT_f);

        // scores = Q K^T / 8 (causal, z = 48)
        gemm_f1<3><<<dim3(TT/BN, TT/BM, BB*HH), 256, SMEM1>>>(
            qkv_f,      (long)TT*3*EE, HDIM, 3*EE,
            qkv_f + EE, (long)TT*3*EE, HDIM, 3*EE,
            att, nullptr, (long)HH*TT*TT, (long)TT*TT, TT,
            nullptr, nullptr, 0,
            TT, TT, HDIM, HH, 0.125f);

        softmax_causal<<<BB*HH*TT, 256>>>(att, p_f);

        // y = P @ V (K trimmed)
        gemm_f1<4><<<dim3(1, TT/BM, BB*HH), 256, SMEM1>>>(
            p_f, (long)HH*TT*TT, (long)TT*TT, TT,
            vT_f, (long)HH*HDIM*TT, (long)HDIM*TT, TT,
            nullptr, y_f, (long)TT*EE, HDIM, EE,
            nullptr, nullptr, 0,
            TT, HDIM, TT, HH, 1.f);

        // x += y @ aproj^T + b
        gemm_f1<2><<<dim3(EE/BN, NROWS/BM, 1), 256, SMEM1>>>(
            y_f, 0, 0, EE,
            pw_f + (long)l*EE*EE, 0, 0, EE,
            x, nullptr, 0, 0, EE,
            aproj_b + (long)l*EE, x, EE,
            NROWS, EE, EE, 1, 1.f);

        layernorm_f16<<<NROWS, 256>>>(x, ln2_w + l*EE, ln2_b + l*EE, xn_f);

        // h = gelu(xn @ fc^T + b) -> fp16
        gemm_f1<1><<<dim3(4*EE/BN, NROWS/BM, 1), 256, SMEM1>>>(
            xn_f, 0, 0, EE,
            fw_f + (long)l*4*EE*EE, 0, 0, EE,
            nullptr, h_f, 0, 0, 4*EE,
            fc_b + (long)l*4*EE, nullptr, 0,
            NROWS, 4*EE, EE, 1, 1.f);

        // x += h @ proj^T + b
        gemm_f1<2><<<dim3(EE/BN, NROWS/BM, 1), 256, SMEM1>>>(
            h_f, 0, 0, 4*EE,
            mw_f + (long)l*4*EE*EE, 0, 0, 4*EE,
            x, nullptr, 0, 0, EE,
            proj_b + (long)l*EE, x, EE,
            NROWS, EE, 4*EE, 1, 1.f);
    }

    layernorm_f16<<<NROWS, 256>>>(x, lnf_w, lnf_b, xn_f);

    // logits = xn @ wte^T -> d_out
    gemm_lm<<<dim3(NROWS/BM, (VV + BN - 1)/BN, 1), 256, SMEM1>>>(
        xn_f, wte_f, out, VV);

    long BTV = (long)NROWS * VV;
    if ((long)out_size > BTV){
        loss_rows<<<NROWS, 256>>>(out, tgt, nll, vld);
        loss_final<<<1, 256>>>(nll, vld, out + BTV);
    }
}

// round 16
// speedup vs baseline: 2.9567x; 1.1720x over previous
#include <cuda_runtime.h>
#include <cuda_fp16.h>
#include <cstdint>
#include <math.h>

// ---------------- problem constants ----------------
#define BB 4
#define TT 1024
#define EE 768
#define HH 12
#define LL 4
#define VV 50257
#define HDIM 64
#define NROWS (BB*TT)          // 4096

// ---------------- scratch (device globals) ----------------
__device__ float g_x  [NROWS*EE];
__device__ float g_nll[NROWS];
__device__ float g_vld[NROWS];

__device__ __half g_xn_f [NROWS*EE];
__device__ __half g_qkv_f[NROWS*3*EE];
__device__ __half g_vT_f [(size_t)BB*HH*HDIM*TT];
__device__ __half g_y_f  [NROWS*EE];
__device__ __half g_h_f  [NROWS*4*EE];

__device__ __half g_wte_f[(size_t)VV*EE];
__device__ __half g_aw_f [LL*3*EE*EE];
__device__ __half g_pw_f [LL*EE*EE];
__device__ __half g_fw_f [LL*4*EE*EE];
__device__ __half g_mw_f [LL*4*EE*EE];

// ---------------- helpers ----------------
__global__ void tohalf4_k(const float4* __restrict__ in, __half2* __restrict__ o, int n4)
{
    int i = blockIdx.x*256 + threadIdx.x;
    if (i >= n4) return;
    float4 v = in[i];
    o[2*i]   = __floats2half2_rn(v.x, v.y);
    o[2*i+1] = __floats2half2_rn(v.z, v.w);
}

__device__ __forceinline__ uint32_t pkh2f(float a, float b){
    __half2 t = __floats2half2_rn(a, b);
    return *reinterpret_cast<uint32_t*>(&t);
}

// ---------------- common GEMM machinery ----------------
#define BM 128
#define BN 128
#define BK 32
#define RS 40
#define OPH (128*RS)
#define NSTAGE 3
#define STG1 (2*OPH)
#define SMEM1 (NSTAGE*STG1*2)   // 61440 bytes

__device__ __forceinline__ void cpa16(uint32_t dst, const void* src, int sz){
    asm volatile("cp.async.cg.shared.global [%0], [%1], 16, %2;\n"
                 :: "r"(dst), "l"(src), "r"(sz));
}
__device__ __forceinline__ void ldsm4(uint32_t& r0, uint32_t& r1, uint32_t& r2,
                                      uint32_t& r3, uint32_t a){
    asm volatile("ldmatrix.sync.aligned.m8n8.x4.shared.b16 {%0,%1,%2,%3}, [%4];\n"
                 : "=r"(r0),"=r"(r1),"=r"(r2),"=r"(r3) : "r"(a));
}
__device__ __forceinline__ void ldsm2(uint32_t& r0, uint32_t& r1, uint32_t a){
    asm volatile("ldmatrix.sync.aligned.m8n8.x2.shared.b16 {%0,%1}, [%2];\n"
                 : "=r"(r0),"=r"(r1) : "r"(a));
}
#define MMA_F16(Cc, A0,A1,A2,A3, B0,B1)                                      \
    asm volatile("mma.sync.aligned.m16n8k16.row.col.f32.f16.f16.f32 "        \
        "{%0,%1,%2,%3}, {%4,%5,%6,%7}, {%8,%9}, {%0,%1,%2,%3};\n"            \
        : "+f"(Cc[0]), "+f"(Cc[1]), "+f"(Cc[2]), "+f"(Cc[3])                 \
        : "r"(A0), "r"(A1), "r"(A2), "r"(A3), "r"(B0), "r"(B1));

// ---------------- layer GEMM: single-pass fp16 (proven R14 kernel) ----------
// MODE: 0 = +bias -> fp16 (QKV)   1 = +bias, GELU -> fp16 (fc)
//       2 = +bias+residual -> f32
template<int MODE>
__global__ void __launch_bounds__(256)
gemm_f1(const __half* __restrict__ A, int lda,
        const __half* __restrict__ B, int ldb,
        float* __restrict__ Cf, __half* __restrict__ Ch, int ldc,
        const float* __restrict__ bias, const float* __restrict__ Res, int ldr,
        int M, int N, int K)
{
    int bn = blockIdx.x, bm = blockIdx.y;
    extern __shared__ __half sm[];
    uint32_t smb = (uint32_t)__cvta_generic_to_shared(sm);
    int KT = K / BK;

    int tid = threadIdx.x;
    const __half* Ab = A + (long)bm*BM*lda;
    const __half* Bb = B + (long)bn*BN*ldb;
    int nbase = bn*BN;

    int seg = tid & 3;
    int row0 = tid >> 2, row1 = (tid + 256) >> 2;

    auto load_stage = [&](int s, int kt){
        int k0 = kt*BK;
        uint32_t base = smb + (uint32_t)s*STG1*2;
        #pragma unroll
        for (int c = 0; c < 2; c++){
            int row = c ? row1 : row0;
            uint32_t so = (uint32_t)(row*RS + seg*8)*2;
            cpa16(base + so, Ab + (long)row*lda + k0 + seg*8, 16);
            int bsz = (nbase + row < N) ? 16 : 0;
            cpa16(base + OPH*2 + so, Bb + (long)row*ldb + k0 + seg*8, bsz);
        }
    };

    load_stage(0, 0);
    asm volatile("cp.async.commit_group;\n");
    load_stage(1, 1);
    asm volatile("cp.async.commit_group;\n");

    float c[4][4][4];
    #pragma unroll
    for (int i=0;i<4;i++)
        #pragma unroll
        for (int j=0;j<4;j++){ c[i][j][0]=0.f;c[i][j][1]=0.f;c[i][j][2]=0.f;c[i][j][3]=0.f; }

    int lane = tid & 31, wid = tid >> 5;
    int wm = (wid >> 2) * 64;
    int wn = (wid & 3) * 32;
    int gq = lane >> 2, tg = lane & 3;
    int aR = lane & 15,        aC = (lane >> 4) * 8;
    int bR = lane & 7,         bC = ((lane >> 3) & 1) * 8;

    for (int kt = 0; kt < KT; kt++){
        __syncthreads();
        if (kt + 2 < KT) load_stage((kt+2)%NSTAGE, kt+2);
        asm volatile("cp.async.commit_group;\n");
        asm volatile("cp.async.wait_group 1;\n");
        __syncthreads();

        uint32_t base  = smb + (uint32_t)(kt % NSTAGE)*STG1*2;
        uint32_t baseA = base, baseB = base + OPH*2;

        #pragma unroll
        for (int ks = 0; ks < 2; ks++){
            int kc0 = ks*16;
            uint32_t af[4][4], bf[4][2];
            #pragma unroll
            for (int i=0;i<4;i++)
                ldsm4(af[i][0],af[i][1],af[i][2],af[i][3],
                      baseA + (uint32_t)((wm + i*16 + aR)*RS + kc0 + aC)*2);
            #pragma unroll
            for (int j=0;j<4;j++)
                ldsm2(bf[j][0],bf[j][1],
                      baseB + (uint32_t)((wn + j*8 + bR)*RS + kc0 + bC)*2);
            #pragma unroll
            for (int i=0;i<4;i++)
                #pragma unroll
                for (int j=0;j<4;j++)
                    MMA_F16(c[i][j], af[i][0],af[i][1],af[i][2],af[i][3], bf[j][0],bf[j][1]);
        }
    }

    #pragma unroll
    for (int i=0;i<4;i++){
        int r0 = bm*BM + wm + i*16 + gq;
        #pragma unroll
        for (int j=0;j<4;j++){
            int c0 = nbase + wn + j*8 + tg*2;
            #pragma unroll
            for (int h2=0; h2<2; h2++){
                int rr = r0 + h2*8;
                #pragma unroll
                for (int cc=0; cc<2; cc++){
                    int col = c0 + cc;
                    if (col >= N) continue;
                    float v = c[i][j][h2*2 + cc];
                    long oidx = (long)rr*ldc + col;
                    if (MODE == 0){
                        Ch[oidx] = __float2half_rn(v + bias[col]);
                    } else if (MODE == 1){
                        v += bias[col];
                        v = 0.5f*v*(1.f + erff(v*0.70710678118654752f));
                        Ch[oidx] = __float2half_rn(v);
                    } else {
                        Cf[oidx] = v + bias[col] + Res[(long)rr*ldr + col];
                    }
                }
            }
        }
    }
}

// ---------------- lm-head GEMM (bm-fastest grid for wte L2 reuse) ------------
__global__ void __launch_bounds__(256)
gemm_lm(const __half* __restrict__ A, const __half* __restrict__ Bm,
        float* __restrict__ C, int N)
{
    int bm = blockIdx.x, bn = blockIdx.y;
    const int K = EE, KT = K / BK;

    extern __shared__ __half sm2[];
    uint32_t smb = (uint32_t)__cvta_generic_to_shared(sm2);

    int tid = threadIdx.x;
    const __half* Ab = A  + (long)bm*BM*K;
    const __half* Bb = Bm + (long)bn*BN*K;
    int nbase = bn*BN;

    int seg = tid & 3;
    int row0 = tid >> 2, row1 = (tid + 256) >> 2;

    auto load_stage = [&](int s, int kt){
        int k0 = kt*BK;
        uint32_t base = smb + (uint32_t)s*STG1*2;
        #pragma unroll
        for (int c = 0; c < 2; c++){
            int row = c ? row1 : row0;
            uint32_t so = (uint32_t)(row*RS + seg*8)*2;
            cpa16(base + so, Ab + (long)row*K + k0 + seg*8, 16);
            int bsz = (nbase + row < N) ? 16 : 0;
            cpa16(base + OPH*2 + so, Bb + (long)row*K + k0 + seg*8, bsz);
        }
    };

    load_stage(0, 0);
    asm volatile("cp.async.commit_group;\n");
    load_stage(1, 1);
    asm volatile("cp.async.commit_group;\n");

    float c[4][4][4];
    #pragma unroll
    for (int i=0;i<4;i++)
        #pragma unroll
        for (int j=0;j<4;j++){ c[i][j][0]=0.f;c[i][j][1]=0.f;c[i][j][2]=0.f;c[i][j][3]=0.f; }

    int lane = tid & 31, wid = tid >> 5;
    int wm = (wid >> 2) * 64;
    int wn = (wid & 3) * 32;
    int gq = lane >> 2, tg = lane & 3;
    int aR = lane & 15,        aC = (lane >> 4) * 8;
    int bR = lane & 7,         bC = ((lane >> 3) & 1) * 8;

    for (int kt = 0; kt < KT; kt++){
        __syncthreads();
        if (kt + 2 < KT) load_stage((kt+2)%NSTAGE, kt+2);
        asm volatile("cp.async.commit_group;\n");
        asm volatile("cp.async.wait_group 1;\n");
        __syncthreads();

        uint32_t base = smb + (uint32_t)(kt % NSTAGE)*STG1*2;
        uint32_t baseA = base, baseB = base + OPH*2;

        #pragma unroll
        for (int ks = 0; ks < 2; ks++){
            int kc0 = ks*16;
            uint32_t af[4][4], bf[4][2];
            #pragma unroll
            for (int i=0;i<4;i++)
                ldsm4(af[i][0],af[i][1],af[i][2],af[i][3],
                      baseA + (uint32_t)((wm + i*16 + aR)*RS + kc0 + aC)*2);
            #pragma unroll
            for (int j=0;j<4;j++)
                ldsm2(bf[j][0],bf[j][1],
                      baseB + (uint32_t)((wn + j*8 + bR)*RS + kc0 + bC)*2);
            #pragma unroll
            for (int i=0;i<4;i++)
                #pragma unroll
                for (int j=0;j<4;j++)
                    MMA_F16(c[i][j], af[i][0],af[i][1],af[i][2],af[i][3], bf[j][0],bf[j][1]);
        }
    }

    #pragma unroll
    for (int i=0;i<4;i++){
        int r0 = bm*BM + wm + i*16 + gq;
        #pragma unroll
        for (int j=0;j<4;j++){
            int c0 = nbase + wn + j*8 + tg*2;
            #pragma unroll
            for (int h2=0; h2<2; h2++){
                long rb = (long)(r0 + h2*8)*VV;
                #pragma unroll
                for (int cc=0; cc<2; cc++){
                    int col = c0 + cc;
                    if (col < N) C[rb + col] = c[i][j][h2*2 + cc];
                }
            }
        }
    }
}

// ---------------- fused causal attention ----------------
// Grid (TT/128, BB*HH). 8 warps, each owns 16 query rows (full 128-key width)
// -> warp-local online softmax, S C-fragments repacked as P A-fragments.
// smem: Q[128][72] + 2 x (K[128][72] + Vt[64][136])
#define QSTR 72
#define VSTR 136
#define AT_QOFF 0
#define AT_STGH (128*QSTR + 64*VSTR)            // 17920 halves per KV stage
#define AT_KOFF(s) (128*QSTR + (s)*AT_STGH)
#define AT_VOFF(s) (128*QSTR + (s)*AT_STGH + 128*QSTR)
#define AT_SMEM ((128*QSTR + 2*AT_STGH)*2)      // 90112 bytes

__global__ void __launch_bounds__(256)
attn_fused(const __half* __restrict__ qkv, const __half* __restrict__ vT,
           __half* __restrict__ y)
{
    int qi = (int)gridDim.x - 1 - blockIdx.x;   // long CTAs first
    int z = blockIdx.y; int b = z/HH, h = z - b*HH;

    extern __shared__ __half asm_[];
    uint32_t smb = (uint32_t)__cvta_generic_to_shared(asm_);

    int tid = threadIdx.x, lane = tid & 31, w = tid >> 5;
    int gq = lane >> 2, tg = lane & 3;
    int aR = lane & 15, aC = (lane >> 4) * 8;
    int bR = lane & 7,  bC = ((lane >> 3) & 1) * 8;

    const __half* Qg = qkv + (long)(b*TT + qi*128)*(3*EE) + h*HDIM;
    const __half* Kg = qkv + EE + (long)b*TT*(3*EE) + h*HDIM;
    const __half* Vg = vT + (long)z*HDIM*TT;

    // ---- loaders (cp.async, 4 x 16B per thread per tile) ----
    auto load_q = [&](){
        #pragma unroll
        for (int i = 0; i < 4; i++){
            int id = tid + i*256;             // 0..1023
            int r = id >> 3, c8 = (id & 7)*8;
            cpa16(smb + (uint32_t)(AT_QOFF + r*QSTR + c8)*2,
                  Qg + (long)r*(3*EE) + c8, 16);
        }
    };
    auto load_kv = [&](int s, int kt){
        long krow0 = (long)kt*128;
        #pragma unroll
        for (int i = 0; i < 4; i++){
            int id = tid + i*256;
            int r = id >> 3, c8 = (id & 7)*8;
            cpa16(smb + (uint32_t)(AT_KOFF(s) + r*QSTR + c8)*2,
                  Kg + (krow0 + r)*(long)(3*EE) + c8, 16);
        }
        #pragma unroll
        for (int i = 0; i < 4; i++){
            int id = tid + i*256;
            int d = id >> 4, c8 = (id & 15)*8;
            cpa16(smb + (uint32_t)(AT_VOFF(s) + d*VSTR + c8)*2,
                  Vg + (long)d*TT + kt*128 + c8, 16);
        }
    };

    load_q();
    load_kv(0, 0);
    asm volatile("cp.async.commit_group;\n");

    uint32_t q[4][4];
    float o[8][4];
    #pragma unroll
    for (int j=0;j<8;j++){ o[j][0]=0.f;o[j][1]=0.f;o[j][2]=0.f;o[j][3]=0.f; }
    float mrun[2] = {-1e30f, -1e30f};
    float lrun[2] = {0.f, 0.f};

    for (int kt = 0; kt <= qi; kt++){
        int s = kt & 1;
        if (kt + 1 <= qi) load_kv((kt+1)&1, kt+1);
        asm volatile("cp.async.commit_group;\n");
        asm volatile("cp.async.wait_group 1;\n");
        __syncthreads();

        if (kt == 0){
            #pragma unroll
            for (int kc = 0; kc < 4; kc++)
                ldsm4(q[kc][0],q[kc][1],q[kc][2],q[kc][3],
                      smb + (uint32_t)(AT_QOFF + (w*16 + aR)*QSTR + kc*16 + aC)*2);
        }

        // ---- S = Q K^T (warp rows w*16..+15, cols 0..127) ----
        float sc[16][4];
        #pragma unroll
        for (int j=0;j<16;j++){ sc[j][0]=0.f;sc[j][1]=0.f;sc[j][2]=0.f;sc[j][3]=0.f; }
        #pragma unroll
        for (int j = 0; j < 16; j++){
            #pragma unroll
            for (int kc = 0; kc < 4; kc++){
                uint32_t kb0, kb1;
                ldsm2(kb0, kb1,
                      smb + (uint32_t)(AT_KOFF(s) + (j*8 + bR)*QSTR + kc*16 + bC)*2);
                MMA_F16(sc[j], q[kc][0],q[kc][1],q[kc][2],q[kc][3], kb0, kb1);
            }
        }

        // ---- scale + causal mask (only the diagonal tile needs it) ----
        if (kt == qi){
            #pragma unroll
            for (int j = 0; j < 16; j++)
                #pragma unroll
                for (int e = 0; e < 4; e++){
                    int h2 = e >> 1, cc = e & 1;
                    int colin = j*8 + tg*2 + cc;
                    int rowin = w*16 + gq + h2*8;
                    sc[j][e] = (colin > rowin) ? -1e30f : sc[j][e]*0.125f;
                }
        } else {
            #pragma unroll
            for (int j = 0; j < 16; j++)
                #pragma unroll
                for (int e = 0; e < 4; e++) sc[j][e] *= 0.125f;
        }

        // ---- online softmax (warp-local: tg group covers all cols) ----
        float mx[2] = {-1e30f, -1e30f};
        #pragma unroll
        for (int j = 0; j < 16; j++){
            mx[0] = fmaxf(mx[0], fmaxf(sc[j][0], sc[j][1]));
            mx[1] = fmaxf(mx[1], fmaxf(sc[j][2], sc[j][3]));
        }
        #pragma unroll
        for (int d = 1; d <= 2; d <<= 1){
            mx[0] = fmaxf(mx[0], __shfl_xor_sync(0xffffffffu, mx[0], d));
            mx[1] = fmaxf(mx[1], __shfl_xor_sync(0xffffffffu, mx[1], d));
        }
        float mnew[2] = { fmaxf(mrun[0], mx[0]), fmaxf(mrun[1], mx[1]) };
        float corr[2] = { __expf(mrun[0] - mnew[0]), __expf(mrun[1] - mnew[1]) };

        float rs[2] = {0.f, 0.f};
        #pragma unroll
        for (int j = 0; j < 16; j++){
            sc[j][0] = __expf(sc[j][0] - mnew[0]);
            sc[j][1] = __expf(sc[j][1] - mnew[0]);
            sc[j][2] = __expf(sc[j][2] - mnew[1]);
            sc[j][3] = __expf(sc[j][3] - mnew[1]);
            rs[0] += sc[j][0] + sc[j][1];
            rs[1] += sc[j][2] + sc[j][3];
        }
        #pragma unroll
        for (int d = 1; d <= 2; d <<= 1){
            rs[0] += __shfl_xor_sync(0xffffffffu, rs[0], d);
            rs[1] += __shfl_xor_sync(0xffffffffu, rs[1], d);
        }
        lrun[0] = lrun[0]*corr[0] + rs[0];
        lrun[1] = lrun[1]*corr[1] + rs[1];
        mrun[0] = mnew[0]; mrun[1] = mnew[1];

        // rescale O
        #pragma unroll
        for (int j = 0; j < 8; j++){
            o[j][0] *= corr[0]; o[j][1] *= corr[0];
            o[j][2] *= corr[1]; o[j][3] *= corr[1];
        }

        // ---- O += P V : P C-fragments -> A-fragments, V^T from smem ----
        #pragma unroll
        for (int kp = 0; kp < 8; kp++){
            uint32_t a0 = pkh2f(sc[2*kp][0],   sc[2*kp][1]);
            uint32_t a1 = pkh2f(sc[2*kp][2],   sc[2*kp][3]);
            uint32_t a2 = pkh2f(sc[2*kp+1][0], sc[2*kp+1][1]);
            uint32_t a3 = pkh2f(sc[2*kp+1][2], sc[2*kp+1][3]);
            #pragma unroll
            for (int n8 = 0; n8 < 8; n8++){
                uint32_t vb0, vb1;
                ldsm2(vb0, vb1,
                      smb + (uint32_t)(AT_VOFF(s) + (n8*8 + bR)*VSTR + kp*16 + bC)*2);
                MMA_F16(o[n8], a0, a1, a2, a3, vb0, vb1);
            }
        }
        __syncthreads();
    }
    asm volatile("cp.async.wait_group 0;\n");

    // ---- epilogue: O /= l -> y fp16 ----
    float inv0 = 1.f / lrun[0], inv1 = 1.f / lrun[1];
    long r0g = (long)(b*TT + qi*128 + w*16 + gq);
    #pragma unroll
    for (int h2 = 0; h2 < 2; h2++){
        long rb = (r0g + h2*8)*EE + h*HDIM;
        float inv = h2 ? inv1 : inv0;
        #pragma unroll
        for (int n8 = 0; n8 < 8; n8++){
            __half2 v2 = __floats2half2_rn(o[n8][h2*2]*inv, o[n8][h2*2+1]*inv);
            *reinterpret_cast<__half2*>(y + rb + n8*8 + tg*2) = v2;
        }
    }
}

// ---------------- embedding ----------------
__global__ void embed_k(const int* __restrict__ idx, const float* __restrict__ wte,
                        const float* __restrict__ wpe, float* __restrict__ x)
{
    int i = blockIdx.x*256 + threadIdx.x;
    if (i >= NROWS*EE) return;
    int row = i / EE, col = i - row*EE;
    int t = row & (TT-1);
    x[i] = wte[(long)idx[row]*EE + col] + wpe[(long)t*EE + col];
}

// ---------------- layernorm -> fp16 ----------------
__global__ void layernorm_f16(const float* __restrict__ x, const float* __restrict__ w,
                              const float* __restrict__ b, __half* __restrict__ o)
{
    int row = blockIdx.x;
    const float* xr = x + (long)row*EE;
    long obase = (long)row*EE;
    int tid = threadIdx.x;
    float v0 = xr[tid], v1 = xr[tid+256], v2 = xr[tid+512];
    float s = v0+v1+v2, q = v0*v0+v1*v1+v2*v2;
    __shared__ float sh1[256], sh2[256];
    sh1[tid]=s; sh2[tid]=q; __syncthreads();
    #pragma unroll
    for (int off=128; off>0; off>>=1){
        if (tid < off){ sh1[tid]+=sh1[tid+off]; sh2[tid]+=sh2[tid+off]; }
        __syncthreads();
    }
    float mean = sh1[0]*(1.f/EE);
    float var  = sh2[0]*(1.f/EE) - mean*mean;
    float rstd = rsqrtf(var + 1e-5f);
    #pragma unroll
    for (int p = 0; p < 3; p++){
        int cidx = tid + p*256;
        float vv = (p==0? v0 : p==1? v1 : v2);
        o[obase+cidx] = __float2half_rn((vv-mean)*rstd*w[cidx] + b[cidx]);
    }
}

// ---------------- V transpose (fp16) ----------------
__global__ void transpose_v(const __half* __restrict__ q, __half* __restrict__ v)
{
    int z = blockIdx.y; int b = z/HH, h = z - b*HH;
    int k0 = blockIdx.x * 64;
    __shared__ __half t[64][72];
    const long sbase = ((long)(b*TT + k0))*(3*EE) + 2*EE + h*HDIM;
    int tid = threadIdx.x;
    #pragma unroll
    for (int i=0;i<16;i++){
        int id = tid + i*256;
        int kr = id >> 6, d = id & 63;
        t[kr][d] = q[sbase + (long)kr*(3*EE) + d];
    }
    __syncthreads();
    long dbase = (long)z*HDIM*TT + k0;
    #pragma unroll
    for (int i=0;i<16;i++){
        int id = tid + i*256;
        int d = id >> 6, kc = id & 63;
        v[dbase + (long)d*TT + kc] = t[kc][d];
    }
}

// ---------------- loss ----------------
__global__ void loss_rows(const float* __restrict__ lg, const int* __restrict__ tgt,
                          float* __restrict__ nll, float* __restrict__ vld)
{
    long row = blockIdx.x;
    const float* p = lg + row*(long)VV;
    int tid = threadIdx.x;
    float m = -3.0e38f, s = 0.f;
    for (int k = tid; k < VV; k += 256){
        float x = p[k];
        if (x > m){ s = s*__expf(m - x) + 1.f; m = x; }
        else s += __expf(x - m);
    }
    __shared__ float sm[256], ss[256];
    sm[tid]=m; ss[tid]=s; __syncthreads();
    #pragma unroll
    for (int off=128; off>0; off>>=1){
        if (tid < off){
            float m2 = sm[tid+off], s2 = ss[tid+off];
            float mm = fmaxf(sm[tid], m2);
            ss[tid] = ss[tid]*__expf(sm[tid]-mm) + s2*__expf(m2-mm);
            sm[tid] = mm;
        }
        __syncthreads();
    }
    if (tid == 0){
        float lse = sm[0] + logf(ss[0]);
        int t = tgt[row];
        if (t != -1){ nll[row] = lse - p[t]; vld[row] = 1.f; }
        else        { nll[row] = 0.f;       vld[row] = 0.f; }
    }
}

__global__ void loss_final(const float* __restrict__ nll, const float* __restrict__ vld,
                           float* __restrict__ out)
{
    int tid = threadIdx.x;
    float a = 0.f, b = 0.f;
    for (int i = tid; i < NROWS; i += 256){ a += nll[i]; b += vld[i]; }
    __shared__ float s1[256], s2[256];
    s1[tid]=a; s2[tid]=b; __syncthreads();
    #pragma unroll
    for (int off=128; off>0; off>>=1){
        if (tid < off){ s1[tid]+=s1[tid+off]; s2[tid]+=s2[tid+off]; }
        __syncthreads();
    }
    if (tid == 0) out[0] = s1[0] / fmaxf(s2[0], 1.f);
}

// ---------------- host ----------------
static void tohalf_arr(const float* src, __half* o, long n){
    int n4 = (int)(n/4);
    tohalf4_k<<<(n4 + 255)/256, 256>>>((const float4*)src, (__half2*)o, n4);
}

extern "C" void kernel_launch(void* const* d_in, const int* in_sizes, int n_in,
                              void* d_out, int out_size)
{
    const int*   idx     = (const int*)  d_in[0];
    const int*   tgt     = (const int*)  d_in[1];
    const float* wte     = (const float*)d_in[2];
    const float* wpe     = (const float*)d_in[3];
    const float* ln1_w   = (const float*)d_in[4];
    const float* ln1_b   = (const float*)d_in[5];
    const float* attn_w  = (const float*)d_in[6];
    const float* attn_b  = (const float*)d_in[7];
    const float* aproj_w = (const float*)d_in[8];
    const float* aproj_b = (const float*)d_in[9];
    const float* ln2_w   = (const float*)d_in[10];
    const float* ln2_b   = (const float*)d_in[11];
    const float* fc_w    = (const float*)d_in[12];
    const float* fc_b    = (const float*)d_in[13];
    const float* proj_w  = (const float*)d_in[14];
    const float* proj_b  = (const float*)d_in[15];
    const float* lnf_w   = (const float*)d_in[16];
    const float* lnf_b   = (const float*)d_in[17];
    float* out = (float*)d_out;

    float *x, *nll, *vld;
    __half *xn_f,*qkv_f,*vT_f,*y_f,*h_f;
    __half *wte_f,*aw_f,*pw_f,*fw_f,*mw_f;
    cudaGetSymbolAddress((void**)&x,    g_x);
    cudaGetSymbolAddress((void**)&nll,  g_nll);
    cudaGetSymbolAddress((void**)&vld,  g_vld);
    cudaGetSymbolAddress((void**)&xn_f, g_xn_f);
    cudaGetSymbolAddress((void**)&qkv_f,g_qkv_f);
    cudaGetSymbolAddress((void**)&vT_f, g_vT_f);
    cudaGetSymbolAddress((void**)&y_f,  g_y_f);
    cudaGetSymbolAddress((void**)&h_f,  g_h_f);
    cudaGetSymbolAddress((void**)&wte_f,g_wte_f);
    cudaGetSymbolAddress((void**)&aw_f, g_aw_f);
    cudaGetSymbolAddress((void**)&pw_f, g_pw_f);
    cudaGetSymbolAddress((void**)&fw_f, g_fw_f);
    cudaGetSymbolAddress((void**)&mw_f, g_mw_f);

    cudaFuncSetAttribute(gemm_f1<0>, cudaFuncAttributeMaxDynamicSharedMemorySize, SMEM1);
    cudaFuncSetAttribute(gemm_f1<1>, cudaFuncAttributeMaxDynamicSharedMemorySize, SMEM1);
    cudaFuncSetAttribute(gemm_f1<2>, cudaFuncAttributeMaxDynamicSharedMemorySize, SMEM1);
    cudaFuncSetAttribute(gemm_lm,    cudaFuncAttributeMaxDynamicSharedMemorySize, SMEM1);
    cudaFuncSetAttribute(attn_fused, cudaFuncAttributeMaxDynamicSharedMemorySize, AT_SMEM);

    // one-shot weight fp16 conversion
    tohalf_arr(attn_w,  aw_f, (long)LL*3*EE*EE);
    tohalf_arr(aproj_w, pw_f, (long)LL*EE*EE);
    tohalf_arr(fc_w,    fw_f, (long)LL*4*EE*EE);
    tohalf_arr(proj_w,  mw_f, (long)LL*4*EE*EE);
    tohalf_arr(wte,     wte_f, (long)VV*EE);

    embed_k<<<(NROWS*EE + 255)/256, 256>>>(idx, wte, wpe, x);

    for (int l = 0; l < LL; l++){
        layernorm_f16<<<NROWS, 256>>>(x, ln1_w + l*EE, ln1_b + l*EE, xn_f);

        // QKV = xn @ attn_w^T + b -> fp16
        gemm_f1<0><<<dim3(3*EE/BN, NROWS/BM), 256, SMEM1>>>(
            xn_f, EE, aw_f + (long)l*3*EE*EE, EE,
            nullptr, qkv_f, 3*EE,
            attn_b + (long)l*3*EE, nullptr, 0,
            NROWS, 3*EE, EE);

        transpose_v<<<dim3(TT/64, BB*HH), 256>>>(qkv_f, vT_f);

        // fused attention: scores + causal softmax + PV -> y fp16
        attn_fused<<<dim3(TT/128, BB*HH), 256, AT_SMEM>>>(qkv_f, vT_f, y_f);

        // x += y @ aproj^T + b
        gemm_f1<2><<<dim3(EE/BN, NROWS/BM), 256, SMEM1>>>(
            y_f, EE, pw_f + (long)l*EE*EE, EE,
            x, nullptr, EE,
            aproj_b + (long)l*EE, x, EE,
            NROWS, EE, EE);

        layernorm_f16<<<NROWS, 256>>>(x, ln2_w + l*EE, ln2_b + l*EE, xn_f);

        // h = gelu(xn @ fc^T + b) -> fp16
        gemm_f1<1><<<dim3(4*EE/BN, NROWS/BM), 256, SMEM1>>>(
            xn_f, EE, fw_f + (long)l*4*EE*EE, EE,
            nullptr, h_f, 4*EE,
            fc_b + (long)l*4*EE, nullptr, 0,
            NROWS, 4*EE, EE);

        // x += h @ proj^T + b
        gemm_f1<2><<<dim3(EE/BN, NROWS/BM), 256, SMEM1>>>(
            h_f, 4*EE, mw_f + (long)l*4*EE*EE, 4*EE,
            x, nullptr, EE,
            proj_b + (long)l*EE, x, EE,
            NROWS, EE, 4*EE);
    }

    layernorm_f16<<<NROWS, 256>>>(x, lnf_w, lnf_b, xn_f);

    // logits = xn @ wte^T -> d_out
    gemm_lm<<<dim3(NROWS/BM, (VV + BN - 1)/BN), 256, SMEM1>>>(
        xn_f, wte_f, out, VV);

    long BTV = (long)NROWS * VV;
    if ((long)out_size > BTV){
        loss_rows<<<NROWS, 256>>>(out, tgt, nll, vld);
        loss_final<<<1, 256>>>(nll, vld, out + BTV);
    }
}